// round 5
// baseline (speedup 1.0000x reference)
#include <cuda_runtime.h>
#include <cuda_bf16.h>
#include <math.h>
#include <stdint.h>

typedef __nv_bfloat16 bf16;

#define T_TOKENS 8192
#define D_DIM    1024
#define E_EXP    8
#define I_DIM    938
#define GU_DIM   1876
#define GUP      1920      // 2I padded (15*128)
#define IP       960       // I padded (15*64)
#define NSLOT    9         // slot0 = shared, 1..8 = routed

#define BM 256
#define BN 128
#define BK 64
#define SROW 144                        // 64 bf16 data + 8 bf16 pad
#define OFF_AH 0
#define OFF_AL (BM*SROW)                // 36864
#define OFF_BH (2*BM*SROW)              // 73728
#define OFF_BL (2*BM*SROW + BN*SROW)    // 92160
#define STAGEB (2*BM*SROW + 2*BN*SROW)  // 110592
#define SMEM_DYN (1024 + 2*STAGEB)      // 222208

// ---------------- static scratch ----------------
__device__ int    g_cnt[E_EXP];
__device__ int    g_tok[E_EXP * T_TOKENS];
__device__ int4   g_tk2[T_TOKENS];
__device__ float2 g_w2 [T_TOKENS];
__device__ bf16   g_xhi[T_TOKENS * D_DIM];
__device__ bf16   g_xlo[T_TOKENS * D_DIM];
__device__ bf16   g_wgu_hi[NSLOT * GUP * D_DIM];   // interleaved (gate_i, up_i) rows
__device__ bf16   g_wgu_lo[NSLOT * GUP * D_DIM];
__device__ bf16   g_wdn_hi[NSLOT * D_DIM * IP];
__device__ bf16   g_wdn_lo[NSLOT * D_DIM * IP];
__device__ bf16   g_act_hi[(size_t)NSLOT * T_TOKENS * IP];
__device__ bf16   g_act_lo[(size_t)NSLOT * T_TOKENS * IP];
__device__ float  g_ybuf[(size_t)E_EXP * T_TOKENS * D_DIM];

// ---------------- helpers ----------------
__device__ __forceinline__ uint32_t smem_u32(const void* p) {
    uint32_t a;
    asm("{ .reg .u64 t; cvta.to.shared.u64 t, %1; cvt.u32.u64 %0, t; }" : "=r"(a) : "l"(p));
    return a;
}
__device__ __forceinline__ void cp16(uint32_t s, const void* g) {
    asm volatile("cp.async.cg.shared.global [%0], [%1], 16;" :: "r"(s), "l"(g));
}
__device__ __forceinline__ void ldsm4(uint32_t* r, uint32_t a) {
    asm volatile("ldmatrix.sync.aligned.m8n8.x4.shared.b16 {%0,%1,%2,%3}, [%4];"
        : "=r"(r[0]), "=r"(r[1]), "=r"(r[2]), "=r"(r[3]) : "r"(a));
}
__device__ __forceinline__ void mma16816(float* d, const uint32_t* a, const uint32_t* b) {
    asm volatile(
        "mma.sync.aligned.m16n8k16.row.col.f32.bf16.bf16.f32 "
        "{%0,%1,%2,%3}, {%4,%5,%6,%7}, {%8,%9}, {%0,%1,%2,%3};"
        : "+f"(d[0]), "+f"(d[1]), "+f"(d[2]), "+f"(d[3])
        : "r"(a[0]), "r"(a[1]), "r"(a[2]), "r"(a[3]), "r"(b[0]), "r"(b[1]));
}
__device__ __forceinline__ void split2(float v, bf16& h, bf16& l) {
    h = __float2bfloat16(v);
    l = __float2bfloat16(v - __bfloat162float(h));
}

// ---------------- mainloop: 256x128 CTA tile, 64x64 warp tile, 3-term split ----------
// Term-major MMA issue: no back-to-back accumulator RAW hazards.
__device__ __forceinline__ void gemm_mainloop(
    uint32_t s0,
    const bf16* sa_h, const bf16* sa_l,   // per-thread A row ptr (row = tid)
    const bf16* sb_h, const bf16* sb_l,   // per-thread B row ptr (row = tid>>1)
    int NC, int tid, float acc[4][8][4])
{
    const int lane = tid & 31, wid = tid >> 5;
    const uint32_t aoff = (uint32_t)tid * SROW;
    const uint32_t boff = (uint32_t)(tid >> 1) * SROW + (uint32_t)(tid & 1) * 64;
    const int bkel = (tid & 1) * 32;

#define LOAD_STAGE(st, c) do {                                              \
        uint32_t base_ = s0 + (st) * STAGEB;                                \
        int k0_ = (c) * BK;                                                 \
        _Pragma("unroll")                                                   \
        for (int j = 0; j < 8; j++) {                                       \
            cp16(base_ + OFF_AH + aoff + j*16, sa_h + k0_ + j*8);           \
            cp16(base_ + OFF_AL + aoff + j*16, sa_l + k0_ + j*8);           \
        }                                                                   \
        _Pragma("unroll")                                                   \
        for (int j = 0; j < 4; j++) {                                       \
            cp16(base_ + OFF_BH + boff + j*16, sb_h + k0_ + bkel + j*8);    \
            cp16(base_ + OFF_BL + boff + j*16, sb_l + k0_ + bkel + j*8);    \
        }                                                                   \
        asm volatile("cp.async.commit_group;" ::: "memory");                \
    } while (0)

    LOAD_STAGE(0, 0);

    const int mwb = (wid >> 1) * 64;
    const int nwb = (wid & 1) * 64;
    const int arow   = mwb + (lane & 15);
    const int acolB0 = (lane >> 4) * 16;
    const int bnrow  = nwb + ((lane >> 4) * 8) + (lane & 7);
    const int bkB0   = ((lane >> 3) & 1) * 16;

    for (int c = 0; c < NC; c++) {
        const int st = c & 1;
        if (c + 1 < NC) {
            LOAD_STAGE(st ^ 1, c + 1);
            asm volatile("cp.async.wait_group 1;" ::: "memory");
        } else {
            asm volatile("cp.async.wait_group 0;" ::: "memory");
        }
        __syncthreads();
        const uint32_t tb = s0 + st * STAGEB;
#pragma unroll
        for (int ks = 0; ks < 4; ks++) {
            const uint32_t acolB = ks * 32 + acolB0;
            const uint32_t bcolB = ks * 32 + bkB0;
            uint32_t ah[4][4], al[4][4];
#pragma unroll
            for (int mi = 0; mi < 4; mi++) {
                uint32_t ra = tb + (uint32_t)(arow + mi * 16) * SROW + acolB;
                ldsm4(ah[mi], ra + OFF_AH);
                ldsm4(al[mi], ra + OFF_AL);
            }
#pragma unroll
            for (int half = 0; half < 2; half++) {
                uint32_t bh[2][4], bl[2][4];
#pragma unroll
                for (int nb = 0; nb < 2; nb++) {
                    uint32_t rb = tb + (uint32_t)(bnrow + (half * 2 + nb) * 16) * SROW + bcolB;
                    ldsm4(bh[nb], rb + OFF_BH);
                    ldsm4(bl[nb], rb + OFF_BL);
                }
                // term 1: Ah*Bh  (16 MMAs, all-distinct accumulators)
#pragma unroll
                for (int mi = 0; mi < 4; mi++)
#pragma unroll
                    for (int nb = 0; nb < 2; nb++) {
                        mma16816(acc[mi][half * 4 + nb * 2 + 0], ah[mi], bh[nb] + 0);
                        mma16816(acc[mi][half * 4 + nb * 2 + 1], ah[mi], bh[nb] + 2);
                    }
                // term 2: Ah*Bl
#pragma unroll
                for (int mi = 0; mi < 4; mi++)
#pragma unroll
                    for (int nb = 0; nb < 2; nb++) {
                        mma16816(acc[mi][half * 4 + nb * 2 + 0], ah[mi], bl[nb] + 0);
                        mma16816(acc[mi][half * 4 + nb * 2 + 1], ah[mi], bl[nb] + 2);
                    }
                // term 3: Al*Bh
#pragma unroll
                for (int mi = 0; mi < 4; mi++)
#pragma unroll
                    for (int nb = 0; nb < 2; nb++) {
                        mma16816(acc[mi][half * 4 + nb * 2 + 0], al[mi], bh[nb] + 0);
                        mma16816(acc[mi][half * 4 + nb * 2 + 1], al[mi], bh[nb] + 2);
                    }
            }
        }
        __syncthreads();
    }
#undef LOAD_STAGE
}

// ---------------- GEMM1: H = X @ Wgu^T, fused swiglu -> act hi/lo ----------------
__global__ void __launch_bounds__(256, 1) gemm1_kernel() {
    extern __shared__ char smem[];
    int* rowids = (int*)smem;
    const uint32_t s0 = smem_u32(smem) + 1024;
    const int tid = threadIdx.x;
    const int s = blockIdx.z, m0 = blockIdx.y * BM, n0 = blockIdx.x * BN;
    const int M = (s == 0) ? T_TOKENS : g_cnt[s - 1];
    if (m0 >= M) return;

    {
        int am = m0 + tid;
        int r;
        if (s == 0) r = (am < M ? am : M - 1);
        else        r = g_tok[(s - 1) * T_TOKENS + (am < M ? am : M - 1)];
        rowids[tid] = r;
    }
    __syncthreads();

    const long long arow = rowids[tid];
    const bf16* sa_h = g_xhi + arow * D_DIM;
    const bf16* sa_l = g_xlo + arow * D_DIM;
    const long long brow = (long long)s * GUP + n0 + (tid >> 1);
    const bf16* sb_h = g_wgu_hi + brow * D_DIM;
    const bf16* sb_l = g_wgu_lo + brow * D_DIM;

    float acc[4][8][4];
#pragma unroll
    for (int i = 0; i < 4; i++)
#pragma unroll
        for (int j = 0; j < 8; j++)
#pragma unroll
            for (int k = 0; k < 4; k++) acc[i][j][k] = 0.f;

    gemm_mainloop(s0, sa_h, sa_l, sb_h, sb_l, D_DIM / BK, tid, acc);

    const int lane = tid & 31, wid = tid >> 5;
    const int mwb = (wid >> 1) * 64, nwb = (wid & 1) * 64;
    bf16* oh = g_act_hi + (size_t)s * T_TOKENS * IP;
    bf16* ol = g_act_lo + (size_t)s * T_TOKENS * IP;
#pragma unroll
    for (int mi = 0; mi < 4; mi++) {
        const int r0 = m0 + mwb + mi * 16 + (lane >> 2);
#pragma unroll
        for (int j = 0; j < 8; j++) {
            const int nbase = n0 + nwb + (j >> 1) * 16 + (j & 1) * 8 + (lane & 3) * 2;
            const int acol = nbase >> 1;
            const float* a = acc[mi][j];
            if (r0 < M) {
                float g = a[0], u = a[1];
                float v = (g / (1.f + __expf(-g))) * u;
                bf16 h, l; split2(v, h, l);
                oh[(size_t)r0 * IP + acol] = h;
                ol[(size_t)r0 * IP + acol] = l;
            }
            if (r0 + 8 < M) {
                float g = a[2], u = a[3];
                float v = (g / (1.f + __expf(-g))) * u;
                bf16 h, l; split2(v, h, l);
                oh[(size_t)(r0 + 8) * IP + acol] = h;
                ol[(size_t)(r0 + 8) * IP + acol] = l;
            }
        }
    }
}

// ---------------- GEMM2: C = act @ down^T (slot0 -> out, 1..8 -> ybuf) ----------
__global__ void __launch_bounds__(256, 1) gemm2_kernel(float* __restrict__ out) {
    extern __shared__ char smem[];
    const uint32_t s0 = smem_u32(smem) + 1024;
    const int tid = threadIdx.x;
    const int s = blockIdx.z, m0 = blockIdx.y * BM, n0 = blockIdx.x * BN;
    const int M = (s == 0) ? T_TOKENS : g_cnt[s - 1];
    if (m0 >= M) return;

    const int amr = m0 + tid < T_TOKENS ? m0 + tid : T_TOKENS - 1;
    const bf16* sa_h = g_act_hi + (size_t)s * T_TOKENS * IP + (size_t)amr * IP;
    const bf16* sa_l = g_act_lo + (size_t)s * T_TOKENS * IP + (size_t)amr * IP;
    const long long brow = (long long)s * D_DIM + n0 + (tid >> 1);
    const bf16* sb_h = g_wdn_hi + brow * IP;
    const bf16* sb_l = g_wdn_lo + brow * IP;

    float acc[4][8][4];
#pragma unroll
    for (int i = 0; i < 4; i++)
#pragma unroll
        for (int j = 0; j < 8; j++)
#pragma unroll
            for (int k = 0; k < 4; k++) acc[i][j][k] = 0.f;

    gemm_mainloop(s0, sa_h, sa_l, sb_h, sb_l, IP / BK, tid, acc);

    float* C = (s == 0) ? out : (g_ybuf + (size_t)(s - 1) * T_TOKENS * D_DIM);
    const int lane = tid & 31, wid = tid >> 5;
    const int mwb = (wid >> 1) * 64, nwb = (wid & 1) * 64;
#pragma unroll
    for (int mi = 0; mi < 4; mi++) {
        const int r0 = m0 + mwb + mi * 16 + (lane >> 2);
#pragma unroll
        for (int j = 0; j < 8; j++) {
            const int n = n0 + nwb + (j >> 1) * 16 + (j & 1) * 8 + (lane & 3) * 2;
            const float* a = acc[mi][j];
            if (r0 < M)     *(float2*)(C + (size_t)r0 * D_DIM + n)       = make_float2(a[0], a[1]);
            if (r0 + 8 < M) *(float2*)(C + (size_t)(r0 + 8) * D_DIM + n) = make_float2(a[2], a[3]);
        }
    }
}

// ---------------- combine: out[t] += w1*y[e1][p1] + w2*y[e2][p2] ----------------
__global__ void combine_kernel(float* __restrict__ out) {
    const int t = blockIdx.x;
    const int c = threadIdx.x;
    const int4 e = g_tk2[t];
    const float2 w = g_w2[t];
    const float4* y1 = (const float4*)(g_ybuf + ((size_t)e.x * T_TOKENS + e.y) * D_DIM);
    const float4* y2 = (const float4*)(g_ybuf + ((size_t)e.z * T_TOKENS + e.w) * D_DIM);
    float4* o = (float4*)(out + (size_t)t * D_DIM);
    float4 a = o[c], b1 = y1[c], b2 = y2[c];
    a.x += w.x * b1.x + w.y * b2.x;
    a.y += w.x * b1.y + w.y * b2.y;
    a.z += w.x * b1.z + w.y * b2.z;
    a.w += w.x * b1.w + w.y * b2.w;
    o[c] = a;
}

// ---------------- prep kernels ----------------
__global__ void zero_cnt_kernel(int* cnt) {
    if (threadIdx.x < E_EXP) cnt[threadIdx.x] = 0;
}

__global__ void split_x_kernel(const float* __restrict__ x, bf16* __restrict__ xh,
                               bf16* __restrict__ xl) {
    const int i4 = (blockIdx.x * 256 + threadIdx.x) * 4;
    float4 v = *(const float4*)(x + i4);
    __align__(8) bf16 h[4], l[4];
    split2(v.x, h[0], l[0]); split2(v.y, h[1], l[1]);
    split2(v.z, h[2], l[2]); split2(v.w, h[3], l[3]);
    *(uint2*)(xh + i4) = *(const uint2*)h;
    *(uint2*)(xl + i4) = *(const uint2*)l;
}

// grid (GUP, NSLOT), block 256
__global__ void repack_wgu_kernel(const float* __restrict__ sgu, const float* __restrict__ egu,
                                  bf16* __restrict__ wh, bf16* __restrict__ wl) {
    const int r = blockIdx.x, s = blockIdx.y;
    const int k4 = threadIdx.x * 4;
    const size_t dst = ((size_t)s * GUP + r) * D_DIM + k4;
    float4 v = make_float4(0.f, 0.f, 0.f, 0.f);
    if (r < GU_DIM) {
        const int sr = (r & 1) ? (r >> 1) + I_DIM : (r >> 1);
        const float* src = (s == 0) ? (sgu + (size_t)sr * D_DIM)
                                    : (egu + ((size_t)(s - 1) * GU_DIM + sr) * D_DIM);
        v = *(const float4*)(src + k4);
    }
    __align__(8) bf16 h[4], l[4];
    split2(v.x, h[0], l[0]); split2(v.y, h[1], l[1]);
    split2(v.z, h[2], l[2]); split2(v.w, h[3], l[3]);
    *(uint2*)(wh + dst) = *(const uint2*)h;
    *(uint2*)(wl + dst) = *(const uint2*)l;
}

// grid (D_DIM, NSLOT), block 240
__global__ void repack_wdn_kernel(const float* __restrict__ sdn, const float* __restrict__ edn,
                                  bf16* __restrict__ wh, bf16* __restrict__ wl) {
    const int n = blockIdx.x, s = blockIdx.y;
    const int k4 = threadIdx.x * 4;
    const size_t dst = ((size_t)s * D_DIM + n) * IP + k4;
    const float* src = (s == 0) ? (sdn + (size_t)n * I_DIM)
                                : (edn + ((size_t)(s - 1) * D_DIM + n) * I_DIM);
    __align__(8) bf16 h[4], l[4];
#pragma unroll
    for (int q = 0; q < 4; q++) {
        const int i = k4 + q;
        float v = (i < I_DIM) ? __ldg(src + i) : 0.f;
        split2(v, h[q], l[q]);
    }
    *(uint2*)(wh + dst) = *(const uint2*)h;
    *(uint2*)(wl + dst) = *(const uint2*)l;
}

// ---------------- router ----------------
__global__ void router_kernel(const float* __restrict__ x, const float* __restrict__ gw,
                              int* __restrict__ cnt, int* __restrict__ tok,
                              int4* __restrict__ tk2, float2* __restrict__ w2) {
    __shared__ float sgw[E_EXP * D_DIM];
    const int tid = threadIdx.x;
    for (int i = tid; i < E_EXP * D_DIM; i += blockDim.x) sgw[i] = gw[i];
    __syncthreads();
    const int warp = tid >> 5, lane = tid & 31;
    const int t = blockIdx.x * 8 + warp;
    const float* xt = x + (long long)t * D_DIM;
    float acc[E_EXP];
#pragma unroll
    for (int e = 0; e < E_EXP; e++) acc[e] = 0.f;
    for (int k = lane; k < D_DIM; k += 32) {
        float xv = xt[k];
#pragma unroll
        for (int e = 0; e < E_EXP; e++) acc[e] += xv * sgw[e * D_DIM + k];
    }
#pragma unroll
    for (int e = 0; e < E_EXP; e++)
#pragma unroll
        for (int off = 16; off; off >>= 1)
            acc[e] += __shfl_xor_sync(0xffffffffu, acc[e], off);
    if (lane == 0) {
        float mx = acc[0];
#pragma unroll
        for (int e = 1; e < E_EXP; e++) mx = fmaxf(mx, acc[e]);
        float p[E_EXP], Z = 0.f;
#pragma unroll
        for (int e = 0; e < E_EXP; e++) { p[e] = expf(acc[e] - mx); Z += p[e]; }
#pragma unroll
        for (int e = 0; e < E_EXP; e++) p[e] /= Z;
        int i1 = 0;
#pragma unroll
        for (int e = 1; e < E_EXP; e++) if (p[e] > p[i1]) i1 = e;
        int i2 = (i1 == 0) ? 1 : 0;
#pragma unroll
        for (int e = 0; e < E_EXP; e++) if (e != i1 && e != i2 && p[e] > p[i2]) i2 = e;
        float denom = p[i1] + p[i2] + 1e-8f;
        int pos1 = atomicAdd(&cnt[i1], 1);
        tok[i1 * T_TOKENS + pos1] = t;
        int pos2 = atomicAdd(&cnt[i2], 1);
        tok[i2 * T_TOKENS + pos2] = t;
        tk2[t] = make_int4(i1, pos1, i2, pos2);
        w2[t]  = make_float2(p[i1] / denom, p[i2] / denom);
    }
}

// ---------------- host launch ----------------
extern "C" void kernel_launch(void* const* d_in, const int* in_sizes, int n_in,
                              void* d_out, int out_size) {
    const float* x   = (const float*)d_in[0];
    const float* gw  = (const float*)d_in[1];
    const float* sgu = (const float*)d_in[2];
    const float* sdn = (const float*)d_in[3];
    const float* egu = (const float*)d_in[4];
    const float* edn = (const float*)d_in[5];
    float* out = (float*)d_out;

    cudaFuncSetAttribute(gemm1_kernel, cudaFuncAttributeMaxDynamicSharedMemorySize, SMEM_DYN);
    cudaFuncSetAttribute(gemm2_kernel, cudaFuncAttributeMaxDynamicSharedMemorySize, SMEM_DYN);

    void *pCnt, *pTok, *pTk2, *pW2, *pXh, *pXl, *pWguH, *pWguL, *pWdnH, *pWdnL;
    cudaGetSymbolAddress(&pCnt, g_cnt);
    cudaGetSymbolAddress(&pTok, g_tok);
    cudaGetSymbolAddress(&pTk2, g_tk2);
    cudaGetSymbolAddress(&pW2,  g_w2);
    cudaGetSymbolAddress(&pXh,  g_xhi);
    cudaGetSymbolAddress(&pXl,  g_xlo);
    cudaGetSymbolAddress(&pWguH, g_wgu_hi);
    cudaGetSymbolAddress(&pWguL, g_wgu_lo);
    cudaGetSymbolAddress(&pWdnH, g_wdn_hi);
    cudaGetSymbolAddress(&pWdnL, g_wdn_lo);

    // 1) router
    zero_cnt_kernel<<<1, 32>>>((int*)pCnt);
    router_kernel<<<T_TOKENS / 8, 256>>>(x, gw, (int*)pCnt, (int*)pTok,
                                         (int4*)pTk2, (float2*)pW2);

    // 2) splits / repacks
    split_x_kernel<<<(T_TOKENS * D_DIM) / 1024, 256>>>(x, (bf16*)pXh, (bf16*)pXl);
    repack_wgu_kernel<<<dim3(GUP, NSLOT), 256>>>(sgu, egu, (bf16*)pWguH, (bf16*)pWguL);
    repack_wdn_kernel<<<dim3(D_DIM, NSLOT), 240>>>(sdn, edn, (bf16*)pWdnH, (bf16*)pWdnL);

    // 3) GEMM1 + fused swiglu (shared + routed)
    gemm1_kernel<<<dim3(GUP / BN, T_TOKENS / BM, NSLOT), 256, SMEM_DYN>>>();

    // 4) GEMM2: slot 0 writes out, slots 1..8 write ybuf
    gemm2_kernel<<<dim3(D_DIM / BN, T_TOKENS / BM, NSLOT), 256, SMEM_DYN>>>(out);

    // 5) combine routed contributions (atomic-free)
    combine_kernel<<<T_TOKENS, 256>>>(out);
}

// round 6
// speedup vs baseline: 2.0457x; 2.0457x over previous
#include <cuda_runtime.h>
#include <cuda_fp16.h>
#include <math.h>
#include <stdint.h>

typedef __half fp16;

#define T_TOKENS 8192
#define D_DIM    1024
#define E_EXP    8
#define I_DIM    938
#define GU_DIM   1876
#define GUP      1920      // 2I padded (15*128)
#define IP       960       // I padded (15*64)
#define NSLOT    9         // slot0 = shared, 1..8 = routed

#define BM 256
#define BN 128
#define BK 64
#define SROW 144                        // 64 fp16 = 128B data + 16B pad
#define OFF_A 0
#define OFF_B (BM*SROW)                 // 36864
#define STAGEB (BM*SROW + BN*SROW)      // 55296
#define SMEM_DYN (1024 + 2*STAGEB)      // 111616

// ---------------- static scratch ----------------
__device__ int    g_cnt[E_EXP];
__device__ int    g_tok[E_EXP * T_TOKENS];
__device__ int4   g_tk2[T_TOKENS];
__device__ float2 g_w2 [T_TOKENS];
__device__ fp16   g_x16[T_TOKENS * D_DIM];
__device__ fp16   g_wgu[NSLOT * GUP * D_DIM];     // interleaved (gate_i, up_i) rows
__device__ fp16   g_wdn[NSLOT * D_DIM * IP];
__device__ fp16   g_act[(size_t)NSLOT * T_TOKENS * IP];
__device__ float  g_ybuf[(size_t)E_EXP * T_TOKENS * D_DIM];

// ---------------- helpers ----------------
__device__ __forceinline__ uint32_t smem_u32(const void* p) {
    uint32_t a;
    asm("{ .reg .u64 t; cvta.to.shared.u64 t, %1; cvt.u32.u64 %0, t; }" : "=r"(a) : "l"(p));
    return a;
}
__device__ __forceinline__ void cp16(uint32_t s, const void* g) {
    asm volatile("cp.async.cg.shared.global [%0], [%1], 16;" :: "r"(s), "l"(g));
}
__device__ __forceinline__ void ldsm4(uint32_t* r, uint32_t a) {
    asm volatile("ldmatrix.sync.aligned.m8n8.x4.shared.b16 {%0,%1,%2,%3}, [%4];"
        : "=r"(r[0]), "=r"(r[1]), "=r"(r[2]), "=r"(r[3]) : "r"(a));
}
__device__ __forceinline__ void mma16816(float* d, const uint32_t* a, const uint32_t* b) {
    asm volatile(
        "mma.sync.aligned.m16n8k16.row.col.f32.f16.f16.f32 "
        "{%0,%1,%2,%3}, {%4,%5,%6,%7}, {%8,%9}, {%0,%1,%2,%3};"
        : "+f"(d[0]), "+f"(d[1]), "+f"(d[2]), "+f"(d[3])
        : "r"(a[0]), "r"(a[1]), "r"(a[2]), "r"(a[3]), "r"(b[0]), "r"(b[1]));
}

// ---------------- mainloop: 256x128 CTA tile, 64x64 warp tile, fp16 single-term ------
__device__ __forceinline__ void gemm_mainloop(
    uint32_t s0,
    const fp16* sa,                       // per-thread A row ptr (row = tid)
    const fp16* sb,                       // per-thread B row ptr (row = tid>>1)
    int NC, int tid, float acc[4][8][4])
{
    const int lane = tid & 31, wid = tid >> 5;
    const uint32_t aoff = (uint32_t)tid * SROW;
    const uint32_t boff = (uint32_t)(tid >> 1) * SROW + (uint32_t)(tid & 1) * 64;
    const int bkel = (tid & 1) * 32;

#define LOAD_STAGE(st, c) do {                                              \
        uint32_t base_ = s0 + (st) * STAGEB;                                \
        int k0_ = (c) * BK;                                                 \
        _Pragma("unroll")                                                   \
        for (int j = 0; j < 8; j++)                                         \
            cp16(base_ + OFF_A + aoff + j*16, sa + k0_ + j*8);              \
        _Pragma("unroll")                                                   \
        for (int j = 0; j < 4; j++)                                         \
            cp16(base_ + OFF_B + boff + j*16, sb + k0_ + bkel + j*8);       \
        asm volatile("cp.async.commit_group;" ::: "memory");                \
    } while (0)

    LOAD_STAGE(0, 0);

    const int mwb = (wid >> 1) * 64;
    const int nwb = (wid & 1) * 64;
    const int arow   = mwb + (lane & 15);
    const int acolB0 = (lane >> 4) * 16;
    const int bnrow  = nwb + ((lane >> 4) * 8) + (lane & 7);
    const int bkB0   = ((lane >> 3) & 1) * 16;

    for (int c = 0; c < NC; c++) {
        const int st = c & 1;
        if (c + 1 < NC) {
            LOAD_STAGE(st ^ 1, c + 1);
            asm volatile("cp.async.wait_group 1;" ::: "memory");
        } else {
            asm volatile("cp.async.wait_group 0;" ::: "memory");
        }
        __syncthreads();
        const uint32_t tb = s0 + st * STAGEB;
#pragma unroll
        for (int ks = 0; ks < 4; ks++) {
            const uint32_t acolB = ks * 32 + acolB0;
            const uint32_t bcolB = ks * 32 + bkB0;
            uint32_t ah[4][4];
#pragma unroll
            for (int mi = 0; mi < 4; mi++)
                ldsm4(ah[mi], tb + OFF_A + (uint32_t)(arow + mi * 16) * SROW + acolB);
#pragma unroll
            for (int nb = 0; nb < 4; nb++) {
                uint32_t bh[4];
                ldsm4(bh, tb + OFF_B + (uint32_t)(bnrow + nb * 16) * SROW + bcolB);
#pragma unroll
                for (int mi = 0; mi < 4; mi++) {
                    mma16816(acc[mi][nb * 2 + 0], ah[mi], bh + 0);
                    mma16816(acc[mi][nb * 2 + 1], ah[mi], bh + 2);
                }
            }
        }
        __syncthreads();
    }
#undef LOAD_STAGE
}

// ---------------- GEMM1: H = X @ Wgu^T, fused swiglu -> act fp16 ----------------
__global__ void __launch_bounds__(256, 1) gemm1_kernel() {
    extern __shared__ char smem[];
    int* rowids = (int*)smem;
    const uint32_t s0 = smem_u32(smem) + 1024;
    const int tid = threadIdx.x;
    const int s = blockIdx.z, m0 = blockIdx.y * BM, n0 = blockIdx.x * BN;
    const int M = (s == 0) ? T_TOKENS : g_cnt[s - 1];
    if (m0 >= M) return;

    {
        int am = m0 + tid;
        int r;
        if (s == 0) r = (am < M ? am : M - 1);
        else        r = g_tok[(s - 1) * T_TOKENS + (am < M ? am : M - 1)];
        rowids[tid] = r;
    }
    __syncthreads();

    const fp16* sa = g_x16 + (long long)rowids[tid] * D_DIM;
    const fp16* sb = g_wgu + ((long long)s * GUP + n0 + (tid >> 1)) * D_DIM;

    float acc[4][8][4];
#pragma unroll
    for (int i = 0; i < 4; i++)
#pragma unroll
        for (int j = 0; j < 8; j++)
#pragma unroll
            for (int k = 0; k < 4; k++) acc[i][j][k] = 0.f;

    gemm_mainloop(s0, sa, sb, D_DIM / BK, tid, acc);

    const int lane = tid & 31, wid = tid >> 5;
    const int mwb = (wid >> 1) * 64, nwb = (wid & 1) * 64;
    fp16* oa = g_act + (size_t)s * T_TOKENS * IP;
#pragma unroll
    for (int mi = 0; mi < 4; mi++) {
        const int r0 = m0 + mwb + mi * 16 + (lane >> 2);
#pragma unroll
        for (int j = 0; j < 8; j++) {
            const int nbase = n0 + nwb + (j >> 1) * 16 + (j & 1) * 8 + (lane & 3) * 2;
            const int acol = nbase >> 1;
            const float* a = acc[mi][j];
            if (r0 < M) {
                float g = a[0], u = a[1];
                float v = (g / (1.f + __expf(-g))) * u;
                oa[(size_t)r0 * IP + acol] = __float2half(v);
            }
            if (r0 + 8 < M) {
                float g = a[2], u = a[3];
                float v = (g / (1.f + __expf(-g))) * u;
                oa[(size_t)(r0 + 8) * IP + acol] = __float2half(v);
            }
        }
    }
}

// ---------------- GEMM2: C = act @ down^T (slot0 -> out, 1..8 -> ybuf) ----------
__global__ void __launch_bounds__(256, 1) gemm2_kernel(float* __restrict__ out) {
    extern __shared__ char smem[];
    const uint32_t s0 = smem_u32(smem) + 1024;
    const int tid = threadIdx.x;
    const int s = blockIdx.z, m0 = blockIdx.y * BM, n0 = blockIdx.x * BN;
    const int M = (s == 0) ? T_TOKENS : g_cnt[s - 1];
    if (m0 >= M) return;

    const int amr = m0 + tid < T_TOKENS ? m0 + tid : T_TOKENS - 1;
    const fp16* sa = g_act + (size_t)s * T_TOKENS * IP + (size_t)amr * IP;
    const fp16* sb = g_wdn + ((long long)s * D_DIM + n0 + (tid >> 1)) * IP;

    float acc[4][8][4];
#pragma unroll
    for (int i = 0; i < 4; i++)
#pragma unroll
        for (int j = 0; j < 8; j++)
#pragma unroll
            for (int k = 0; k < 4; k++) acc[i][j][k] = 0.f;

    gemm_mainloop(s0, sa, sb, IP / BK, tid, acc);

    float* C = (s == 0) ? out : (g_ybuf + (size_t)(s - 1) * T_TOKENS * D_DIM);
    const int lane = tid & 31, wid = tid >> 5;
    const int mwb = (wid >> 1) * 64, nwb = (wid & 1) * 64;
#pragma unroll
    for (int mi = 0; mi < 4; mi++) {
        const int r0 = m0 + mwb + mi * 16 + (lane >> 2);
#pragma unroll
        for (int j = 0; j < 8; j++) {
            const int n = n0 + nwb + (j >> 1) * 16 + (j & 1) * 8 + (lane & 3) * 2;
            const float* a = acc[mi][j];
            if (r0 < M)     *(float2*)(C + (size_t)r0 * D_DIM + n)       = make_float2(a[0], a[1]);
            if (r0 + 8 < M) *(float2*)(C + (size_t)(r0 + 8) * D_DIM + n) = make_float2(a[2], a[3]);
        }
    }
}

// ---------------- combine: out[t] += w1*y[e1][p1] + w2*y[e2][p2] ----------------
__global__ void combine_kernel(float* __restrict__ out) {
    const int t = blockIdx.x;
    const int c = threadIdx.x;
    const int4 e = g_tk2[t];
    const float2 w = g_w2[t];
    const float4* y1 = (const float4*)(g_ybuf + ((size_t)e.x * T_TOKENS + e.y) * D_DIM);
    const float4* y2 = (const float4*)(g_ybuf + ((size_t)e.z * T_TOKENS + e.w) * D_DIM);
    float4* o = (float4*)(out + (size_t)t * D_DIM);
    float4 a = o[c], b1 = y1[c], b2 = y2[c];
    a.x += w.x * b1.x + w.y * b2.x;
    a.y += w.x * b1.y + w.y * b2.y;
    a.z += w.x * b1.z + w.y * b2.z;
    a.w += w.x * b1.w + w.y * b2.w;
    o[c] = a;
}

// ---------------- prep kernels ----------------
__global__ void zero_cnt_kernel(int* cnt) {
    if (threadIdx.x < E_EXP) cnt[threadIdx.x] = 0;
}

__global__ void cvt_x_kernel(const float* __restrict__ x, fp16* __restrict__ xo) {
    const int i4 = (blockIdx.x * 256 + threadIdx.x) * 4;
    float4 v = *(const float4*)(x + i4);
    __align__(8) fp16 h[4];
    h[0] = __float2half(v.x); h[1] = __float2half(v.y);
    h[2] = __float2half(v.z); h[3] = __float2half(v.w);
    *(uint2*)(xo + i4) = *(const uint2*)h;
}

// grid (GUP, NSLOT), block 256
__global__ void repack_wgu_kernel(const float* __restrict__ sgu, const float* __restrict__ egu,
                                  fp16* __restrict__ w) {
    const int r = blockIdx.x, s = blockIdx.y;
    const int k4 = threadIdx.x * 4;
    const size_t dst = ((size_t)s * GUP + r) * D_DIM + k4;
    float4 v = make_float4(0.f, 0.f, 0.f, 0.f);
    if (r < GU_DIM) {
        const int sr = (r & 1) ? (r >> 1) + I_DIM : (r >> 1);
        const float* src = (s == 0) ? (sgu + (size_t)sr * D_DIM)
                                    : (egu + ((size_t)(s - 1) * GU_DIM + sr) * D_DIM);
        v = *(const float4*)(src + k4);
    }
    __align__(8) fp16 h[4];
    h[0] = __float2half(v.x); h[1] = __float2half(v.y);
    h[2] = __float2half(v.z); h[3] = __float2half(v.w);
    *(uint2*)(w + dst) = *(const uint2*)h;
}

// grid (D_DIM, NSLOT), block 240
__global__ void repack_wdn_kernel(const float* __restrict__ sdn, const float* __restrict__ edn,
                                  fp16* __restrict__ w) {
    const int n = blockIdx.x, s = blockIdx.y;
    const int k4 = threadIdx.x * 4;
    const size_t dst = ((size_t)s * D_DIM + n) * IP + k4;
    const float* src = (s == 0) ? (sdn + (size_t)n * I_DIM)
                                : (edn + ((size_t)(s - 1) * D_DIM + n) * I_DIM);
    __align__(8) fp16 h[4];
#pragma unroll
    for (int q = 0; q < 4; q++) {
        const int i = k4 + q;
        float v = (i < I_DIM) ? __ldg(src + i) : 0.f;
        h[q] = __float2half(v);
    }
    *(uint2*)(w + dst) = *(const uint2*)h;
}

// ---------------- router (fp32, bit-identical routing) ----------------
__global__ void router_kernel(const float* __restrict__ x, const float* __restrict__ gw,
                              int* __restrict__ cnt, int* __restrict__ tok,
                              int4* __restrict__ tk2, float2* __restrict__ w2) {
    __shared__ float sgw[E_EXP * D_DIM];
    const int tid = threadIdx.x;
    for (int i = tid; i < E_EXP * D_DIM; i += blockDim.x) sgw[i] = gw[i];
    __syncthreads();
    const int warp = tid >> 5, lane = tid & 31;
    const int t = blockIdx.x * 8 + warp;
    const float* xt = x + (long long)t * D_DIM;
    float acc[E_EXP];
#pragma unroll
    for (int e = 0; e < E_EXP; e++) acc[e] = 0.f;
    for (int k = lane; k < D_DIM; k += 32) {
        float xv = xt[k];
#pragma unroll
        for (int e = 0; e < E_EXP; e++) acc[e] += xv * sgw[e * D_DIM + k];
    }
#pragma unroll
    for (int e = 0; e < E_EXP; e++)
#pragma unroll
        for (int off = 16; off; off >>= 1)
            acc[e] += __shfl_xor_sync(0xffffffffu, acc[e], off);
    if (lane == 0) {
        float mx = acc[0];
#pragma unroll
        for (int e = 1; e < E_EXP; e++) mx = fmaxf(mx, acc[e]);
        float p[E_EXP], Z = 0.f;
#pragma unroll
        for (int e = 0; e < E_EXP; e++) { p[e] = expf(acc[e] - mx); Z += p[e]; }
#pragma unroll
        for (int e = 0; e < E_EXP; e++) p[e] /= Z;
        int i1 = 0;
#pragma unroll
        for (int e = 1; e < E_EXP; e++) if (p[e] > p[i1]) i1 = e;
        int i2 = (i1 == 0) ? 1 : 0;
#pragma unroll
        for (int e = 0; e < E_EXP; e++) if (e != i1 && e != i2 && p[e] > p[i2]) i2 = e;
        float denom = p[i1] + p[i2] + 1e-8f;
        int pos1 = atomicAdd(&cnt[i1], 1);
        tok[i1 * T_TOKENS + pos1] = t;
        int pos2 = atomicAdd(&cnt[i2], 1);
        tok[i2 * T_TOKENS + pos2] = t;
        tk2[t] = make_int4(i1, pos1, i2, pos2);
        w2[t]  = make_float2(p[i1] / denom, p[i2] / denom);
    }
}

// ---------------- host launch ----------------
extern "C" void kernel_launch(void* const* d_in, const int* in_sizes, int n_in,
                              void* d_out, int out_size) {
    const float* x   = (const float*)d_in[0];
    const float* gw  = (const float*)d_in[1];
    const float* sgu = (const float*)d_in[2];
    const float* sdn = (const float*)d_in[3];
    const float* egu = (const float*)d_in[4];
    const float* edn = (const float*)d_in[5];
    float* out = (float*)d_out;

    cudaFuncSetAttribute(gemm1_kernel, cudaFuncAttributeMaxDynamicSharedMemorySize, SMEM_DYN);
    cudaFuncSetAttribute(gemm2_kernel, cudaFuncAttributeMaxDynamicSharedMemorySize, SMEM_DYN);

    void *pCnt, *pTok, *pTk2, *pW2, *pX16, *pWgu, *pWdn;
    cudaGetSymbolAddress(&pCnt, g_cnt);
    cudaGetSymbolAddress(&pTok, g_tok);
    cudaGetSymbolAddress(&pTk2, g_tk2);
    cudaGetSymbolAddress(&pW2,  g_w2);
    cudaGetSymbolAddress(&pX16, g_x16);
    cudaGetSymbolAddress(&pWgu, g_wgu);
    cudaGetSymbolAddress(&pWdn, g_wdn);

    // 1) router
    zero_cnt_kernel<<<1, 32>>>((int*)pCnt);
    router_kernel<<<T_TOKENS / 8, 256>>>(x, gw, (int*)pCnt, (int*)pTok,
                                         (int4*)pTk2, (float2*)pW2);

    // 2) conversions / repacks
    cvt_x_kernel<<<(T_TOKENS * D_DIM) / 1024, 256>>>(x, (fp16*)pX16);
    repack_wgu_kernel<<<dim3(GUP, NSLOT), 256>>>(sgu, egu, (fp16*)pWgu);
    repack_wdn_kernel<<<dim3(D_DIM, NSLOT), 240>>>(sdn, edn, (fp16*)pWdn);

    // 3) GEMM1 + fused swiglu (shared + routed)
    gemm1_kernel<<<dim3(GUP / BN, T_TOKENS / BM, NSLOT), 256, SMEM_DYN>>>();

    // 4) GEMM2: slot 0 writes out, slots 1..8 write ybuf
    gemm2_kernel<<<dim3(D_DIM / BN, T_TOKENS / BM, NSLOT), 256, SMEM_DYN>>>(out);

    // 5) combine routed contributions (atomic-free)
    combine_kernel<<<T_TOKENS, 256>>>(out);
}

// round 7
// speedup vs baseline: 2.4468x; 1.1960x over previous
#include <cuda_runtime.h>
#include <cuda_fp16.h>
#include <math.h>
#include <stdint.h>

typedef __half fp16;

#define T_TOKENS 8192
#define D_DIM    1024
#define E_EXP    8
#define I_DIM    938
#define GU_DIM   1876
#define GUP      1920      // 2I padded (15*128)
#define IP       960       // I padded (15*64)
#define NSLOT    9         // slot0 = shared, 1..8 = routed

#define BM 128
#define BN 128
#define BK 64
#define SROW 144                        // 64 fp16 = 128B data + 16B pad
#define OFF_A 0
#define OFF_B (BM*SROW)                 // 18432
#define STAGEB ((BM+BN)*SROW)           // 36864
#define SMEM_DYN (1024 + 2*STAGEB)      // 74752

// ---------------- static scratch ----------------
__device__ int    g_cnt[E_EXP];
__device__ int    g_tok[E_EXP * T_TOKENS];
__device__ int4   g_tk2[T_TOKENS];
__device__ float2 g_w2 [T_TOKENS];
__device__ fp16   g_x16[T_TOKENS * D_DIM];
__device__ fp16   g_wgu[NSLOT * GUP * D_DIM];     // interleaved (gate_i, up_i) rows
__device__ fp16   g_wdn[NSLOT * D_DIM * IP];
__device__ fp16   g_act[(size_t)NSLOT * T_TOKENS * IP];
__device__ fp16   g_ybuf[(size_t)E_EXP * T_TOKENS * D_DIM];

// ---------------- helpers ----------------
__device__ __forceinline__ uint32_t smem_u32(const void* p) {
    uint32_t a;
    asm("{ .reg .u64 t; cvta.to.shared.u64 t, %1; cvt.u32.u64 %0, t; }" : "=r"(a) : "l"(p));
    return a;
}
__device__ __forceinline__ void cp16(uint32_t s, const void* g) {
    asm volatile("cp.async.cg.shared.global [%0], [%1], 16;" :: "r"(s), "l"(g));
}
__device__ __forceinline__ void ldsm4(uint32_t* r, uint32_t a) {
    asm volatile("ldmatrix.sync.aligned.m8n8.x4.shared.b16 {%0,%1,%2,%3}, [%4];"
        : "=r"(r[0]), "=r"(r[1]), "=r"(r[2]), "=r"(r[3]) : "r"(a));
}
__device__ __forceinline__ void mma16816(float* d, const uint32_t* a, const uint32_t* b) {
    asm volatile(
        "mma.sync.aligned.m16n8k16.row.col.f32.f16.f16.f32 "
        "{%0,%1,%2,%3}, {%4,%5,%6,%7}, {%8,%9}, {%0,%1,%2,%3};"
        : "+f"(d[0]), "+f"(d[1]), "+f"(d[2]), "+f"(d[3])
        : "r"(a[0]), "r"(a[1]), "r"(a[2]), "r"(a[3]), "r"(b[0]), "r"(b[1]));
}

// ---------------- mainloop: 128x128 CTA tile, 64x32 warp tile (2x4 warps) -------------
__device__ __forceinline__ void gemm_mainloop(
    uint32_t s0,
    const fp16* sa,                       // per-thread A row ptr (row = tid>>1)
    const fp16* sb,                       // per-thread B row ptr (row = tid>>1)
    int NC, int tid, float acc[4][4][4])
{
    const int lane = tid & 31, wid = tid >> 5;
    const uint32_t rowoff = (uint32_t)(tid >> 1) * SROW + (uint32_t)(tid & 1) * 64;
    const int kel = (tid & 1) * 32;

#define LOAD_STAGE(st, c) do {                                              \
        uint32_t base_ = s0 + (st) * STAGEB;                                \
        int k0_ = (c) * BK + kel;                                           \
        _Pragma("unroll")                                                   \
        for (int j = 0; j < 4; j++) {                                       \
            cp16(base_ + OFF_A + rowoff + j*16, sa + k0_ + j*8);            \
            cp16(base_ + OFF_B + rowoff + j*16, sb + k0_ + j*8);            \
        }                                                                   \
        asm volatile("cp.async.commit_group;" ::: "memory");                \
    } while (0)

    LOAD_STAGE(0, 0);

    const int mwb = (wid >> 2) * 64;
    const int nwb = (wid & 3) * 32;
    const int arow   = mwb + (lane & 15);
    const int acolB0 = (lane >> 4) * 16;
    const int bnrow  = nwb + ((lane >> 4) * 8) + (lane & 7);
    const int bkB0   = ((lane >> 3) & 1) * 16;

    for (int c = 0; c < NC; c++) {
        const int st = c & 1;
        if (c + 1 < NC) {
            LOAD_STAGE(st ^ 1, c + 1);
            asm volatile("cp.async.wait_group 1;" ::: "memory");
        } else {
            asm volatile("cp.async.wait_group 0;" ::: "memory");
        }
        __syncthreads();
        const uint32_t tb = s0 + st * STAGEB;
#pragma unroll
        for (int ks = 0; ks < 4; ks++) {
            const uint32_t acolB = ks * 32 + acolB0;
            const uint32_t bcolB = ks * 32 + bkB0;
            uint32_t ah[4][4];
#pragma unroll
            for (int mi = 0; mi < 4; mi++)
                ldsm4(ah[mi], tb + OFF_A + (uint32_t)(arow + mi * 16) * SROW + acolB);
#pragma unroll
            for (int nb = 0; nb < 2; nb++) {
                uint32_t bh[4];
                ldsm4(bh, tb + OFF_B + (uint32_t)(bnrow + nb * 16) * SROW + bcolB);
#pragma unroll
                for (int mi = 0; mi < 4; mi++) {
                    mma16816(acc[mi][nb * 2 + 0], ah[mi], bh + 0);
                    mma16816(acc[mi][nb * 2 + 1], ah[mi], bh + 2);
                }
            }
        }
        __syncthreads();
    }
#undef LOAD_STAGE
}

// ---------------- GEMM1: H = X @ Wgu^T, fused swiglu -> act fp16 ----------------
__global__ void __launch_bounds__(256, 2) gemm1_kernel() {
    extern __shared__ char smem[];
    int* rowids = (int*)smem;
    const uint32_t s0 = smem_u32(smem) + 1024;
    const int tid = threadIdx.x;
    const int s = blockIdx.z, m0 = blockIdx.y * BM, n0 = blockIdx.x * BN;
    const int M = (s == 0) ? T_TOKENS : g_cnt[s - 1];
    if (m0 >= M) return;

    if (tid < BM) {
        int am = m0 + tid;
        int r;
        if (s == 0) r = (am < M ? am : M - 1);
        else        r = g_tok[(s - 1) * T_TOKENS + (am < M ? am : M - 1)];
        rowids[tid] = r;
    }
    __syncthreads();

    const fp16* sa = g_x16 + (long long)rowids[tid >> 1] * D_DIM;
    const fp16* sb = g_wgu + ((long long)s * GUP + n0 + (tid >> 1)) * D_DIM;

    float acc[4][4][4];
#pragma unroll
    for (int i = 0; i < 4; i++)
#pragma unroll
        for (int j = 0; j < 4; j++)
#pragma unroll
            for (int k = 0; k < 4; k++) acc[i][j][k] = 0.f;

    gemm_mainloop(s0, sa, sb, D_DIM / BK, tid, acc);

    const int lane = tid & 31, wid = tid >> 5;
    const int mwb = (wid >> 2) * 64, nwb = (wid & 3) * 32;
    fp16* oa = g_act + (size_t)s * T_TOKENS * IP;
#pragma unroll
    for (int mi = 0; mi < 4; mi++) {
        const int r0 = m0 + mwb + mi * 16 + (lane >> 2);
#pragma unroll
        for (int j = 0; j < 4; j++) {
            const int nbase = n0 + nwb + j * 8 + (lane & 3) * 2;
            const int acol = nbase >> 1;
            const float* a = acc[mi][j];
            if (r0 < M) {
                float g = a[0], u = a[1];
                float v = (g / (1.f + __expf(-g))) * u;
                oa[(size_t)r0 * IP + acol] = __float2half(v);
            }
            if (r0 + 8 < M) {
                float g = a[2], u = a[3];
                float v = (g / (1.f + __expf(-g))) * u;
                oa[(size_t)(r0 + 8) * IP + acol] = __float2half(v);
            }
        }
    }
}

// ---------------- GEMM2: C = act @ down^T (slot0 -> out fp32, 1..8 -> ybuf fp16) ------
__global__ void __launch_bounds__(256, 2) gemm2_kernel(float* __restrict__ out) {
    extern __shared__ char smem[];
    const uint32_t s0 = smem_u32(smem) + 1024;
    const int tid = threadIdx.x;
    const int s = blockIdx.z, m0 = blockIdx.y * BM, n0 = blockIdx.x * BN;
    const int M = (s == 0) ? T_TOKENS : g_cnt[s - 1];
    if (m0 >= M) return;

    const int amr = m0 + (tid >> 1) < T_TOKENS ? m0 + (tid >> 1) : T_TOKENS - 1;
    const fp16* sa = g_act + (size_t)s * T_TOKENS * IP + (size_t)amr * IP;
    const fp16* sb = g_wdn + ((long long)s * D_DIM + n0 + (tid >> 1)) * IP;

    float acc[4][4][4];
#pragma unroll
    for (int i = 0; i < 4; i++)
#pragma unroll
        for (int j = 0; j < 4; j++)
#pragma unroll
            for (int k = 0; k < 4; k++) acc[i][j][k] = 0.f;

    gemm_mainloop(s0, sa, sb, IP / BK, tid, acc);

    const int lane = tid & 31, wid = tid >> 5;
    const int mwb = (wid >> 2) * 64, nwb = (wid & 3) * 32;
    if (s == 0) {
#pragma unroll
        for (int mi = 0; mi < 4; mi++) {
            const int r0 = m0 + mwb + mi * 16 + (lane >> 2);
#pragma unroll
            for (int j = 0; j < 4; j++) {
                const int n = n0 + nwb + j * 8 + (lane & 3) * 2;
                const float* a = acc[mi][j];
                if (r0 < M)     *(float2*)(out + (size_t)r0 * D_DIM + n)       = make_float2(a[0], a[1]);
                if (r0 + 8 < M) *(float2*)(out + (size_t)(r0 + 8) * D_DIM + n) = make_float2(a[2], a[3]);
            }
        }
    } else {
        fp16* C = g_ybuf + (size_t)(s - 1) * T_TOKENS * D_DIM;
#pragma unroll
        for (int mi = 0; mi < 4; mi++) {
            const int r0 = m0 + mwb + mi * 16 + (lane >> 2);
#pragma unroll
            for (int j = 0; j < 4; j++) {
                const int n = n0 + nwb + j * 8 + (lane & 3) * 2;
                const float* a = acc[mi][j];
                if (r0 < M) {
                    __align__(4) fp16 h[2] = {__float2half(a[0]), __float2half(a[1])};
                    *(uint32_t*)(C + (size_t)r0 * D_DIM + n) = *(const uint32_t*)h;
                }
                if (r0 + 8 < M) {
                    __align__(4) fp16 h[2] = {__float2half(a[2]), __float2half(a[3])};
                    *(uint32_t*)(C + (size_t)(r0 + 8) * D_DIM + n) = *(const uint32_t*)h;
                }
            }
        }
    }
}

// ---------------- combine: out[t] += w1*y[e1][p1] + w2*y[e2][p2] (fp16 ybuf) ----------
__global__ void combine_kernel(float* __restrict__ out) {
    const int t = blockIdx.x;
    const int c = threadIdx.x;                // 256 threads x 4 floats = 1024
    const int4 e = g_tk2[t];
    const float2 w = g_w2[t];
    const uint2* y1 = (const uint2*)(g_ybuf + ((size_t)e.x * T_TOKENS + e.y) * D_DIM);
    const uint2* y2 = (const uint2*)(g_ybuf + ((size_t)e.z * T_TOKENS + e.w) * D_DIM);
    float4* o = (float4*)(out + (size_t)t * D_DIM);
    uint2 p1 = y1[c], p2 = y2[c];
    float2 a1 = __half22float2(*(const __half2*)&p1.x);
    float2 b1 = __half22float2(*(const __half2*)&p1.y);
    float2 a2 = __half22float2(*(const __half2*)&p2.x);
    float2 b2 = __half22float2(*(const __half2*)&p2.y);
    float4 a = o[c];
    a.x += w.x * a1.x + w.y * a2.x;
    a.y += w.x * a1.y + w.y * a2.y;
    a.z += w.x * b1.x + w.y * b2.x;
    a.w += w.x * b1.y + w.y * b2.y;
    o[c] = a;
}

// ---------------- prep kernels ----------------
__global__ void zero_cnt_kernel(int* cnt) {
    if (threadIdx.x < E_EXP) cnt[threadIdx.x] = 0;
}

__global__ void cvt_x_kernel(const float* __restrict__ x, fp16* __restrict__ xo) {
    const int i4 = (blockIdx.x * 256 + threadIdx.x) * 4;
    float4 v = *(const float4*)(x + i4);
    __align__(8) fp16 h[4];
    h[0] = __float2half(v.x); h[1] = __float2half(v.y);
    h[2] = __float2half(v.z); h[3] = __float2half(v.w);
    *(uint2*)(xo + i4) = *(const uint2*)h;
}

// grid (GUP, NSLOT), block 256
__global__ void repack_wgu_kernel(const float* __restrict__ sgu, const float* __restrict__ egu,
                                  fp16* __restrict__ w) {
    const int r = blockIdx.x, s = blockIdx.y;
    const int k4 = threadIdx.x * 4;
    const size_t dst = ((size_t)s * GUP + r) * D_DIM + k4;
    float4 v = make_float4(0.f, 0.f, 0.f, 0.f);
    if (r < GU_DIM) {
        const int sr = (r & 1) ? (r >> 1) + I_DIM : (r >> 1);
        const float* src = (s == 0) ? (sgu + (size_t)sr * D_DIM)
                                    : (egu + ((size_t)(s - 1) * GU_DIM + sr) * D_DIM);
        v = *(const float4*)(src + k4);
    }
    __align__(8) fp16 h[4];
    h[0] = __float2half(v.x); h[1] = __float2half(v.y);
    h[2] = __float2half(v.z); h[3] = __float2half(v.w);
    *(uint2*)(w + dst) = *(const uint2*)h;
}

// grid (D_DIM, NSLOT), block 240
__global__ void repack_wdn_kernel(const float* __restrict__ sdn, const float* __restrict__ edn,
                                  fp16* __restrict__ w) {
    const int n = blockIdx.x, s = blockIdx.y;
    const int k4 = threadIdx.x * 4;
    const size_t dst = ((size_t)s * D_DIM + n) * IP + k4;
    const float* src = (s == 0) ? (sdn + (size_t)n * I_DIM)
                                : (edn + ((size_t)(s - 1) * D_DIM + n) * I_DIM);
    __align__(8) fp16 h[4];
#pragma unroll
    for (int q = 0; q < 4; q++) {
        const int i = k4 + q;
        float v = (i < I_DIM) ? __ldg(src + i) : 0.f;
        h[q] = __float2half(v);
    }
    *(uint2*)(w + dst) = *(const uint2*)h;
}

// ---------------- router (fp32, bit-identical routing) ----------------
__global__ void router_kernel(const float* __restrict__ x, const float* __restrict__ gw,
                              int* __restrict__ cnt, int* __restrict__ tok,
                              int4* __restrict__ tk2, float2* __restrict__ w2) {
    __shared__ float sgw[E_EXP * D_DIM];
    const int tid = threadIdx.x;
    for (int i = tid; i < E_EXP * D_DIM; i += blockDim.x) sgw[i] = gw[i];
    __syncthreads();
    const int warp = tid >> 5, lane = tid & 31;
    const int t = blockIdx.x * 8 + warp;
    const float* xt = x + (long long)t * D_DIM;
    float acc[E_EXP];
#pragma unroll
    for (int e = 0; e < E_EXP; e++) acc[e] = 0.f;
    for (int k = lane; k < D_DIM; k += 32) {
        float xv = xt[k];
#pragma unroll
        for (int e = 0; e < E_EXP; e++) acc[e] += xv * sgw[e * D_DIM + k];
    }
#pragma unroll
    for (int e = 0; e < E_EXP; e++)
#pragma unroll
        for (int off = 16; off; off >>= 1)
            acc[e] += __shfl_xor_sync(0xffffffffu, acc[e], off);
    if (lane == 0) {
        float mx = acc[0];
#pragma unroll
        for (int e = 1; e < E_EXP; e++) mx = fmaxf(mx, acc[e]);
        float p[E_EXP], Z = 0.f;
#pragma unroll
        for (int e = 0; e < E_EXP; e++) { p[e] = expf(acc[e] - mx); Z += p[e]; }
#pragma unroll
        for (int e = 0; e < E_EXP; e++) p[e] /= Z;
        int i1 = 0;
#pragma unroll
        for (int e = 1; e < E_EXP; e++) if (p[e] > p[i1]) i1 = e;
        int i2 = (i1 == 0) ? 1 : 0;
#pragma unroll
        for (int e = 0; e < E_EXP; e++) if (e != i1 && e != i2 && p[e] > p[i2]) i2 = e;
        float denom = p[i1] + p[i2] + 1e-8f;
        int pos1 = atomicAdd(&cnt[i1], 1);
        tok[i1 * T_TOKENS + pos1] = t;
        int pos2 = atomicAdd(&cnt[i2], 1);
        tok[i2 * T_TOKENS + pos2] = t;
        tk2[t] = make_int4(i1, pos1, i2, pos2);
        w2[t]  = make_float2(p[i1] / denom, p[i2] / denom);
    }
}

// ---------------- host launch ----------------
extern "C" void kernel_launch(void* const* d_in, const int* in_sizes, int n_in,
                              void* d_out, int out_size) {
    const float* x   = (const float*)d_in[0];
    const float* gw  = (const float*)d_in[1];
    const float* sgu = (const float*)d_in[2];
    const float* sdn = (const float*)d_in[3];
    const float* egu = (const float*)d_in[4];
    const float* edn = (const float*)d_in[5];
    float* out = (float*)d_out;

    cudaFuncSetAttribute(gemm1_kernel, cudaFuncAttributeMaxDynamicSharedMemorySize, SMEM_DYN);
    cudaFuncSetAttribute(gemm2_kernel, cudaFuncAttributeMaxDynamicSharedMemorySize, SMEM_DYN);

    void *pCnt, *pTok, *pTk2, *pW2, *pX16, *pWgu, *pWdn;
    cudaGetSymbolAddress(&pCnt, g_cnt);
    cudaGetSymbolAddress(&pTok, g_tok);
    cudaGetSymbolAddress(&pTk2, g_tk2);
    cudaGetSymbolAddress(&pW2,  g_w2);
    cudaGetSymbolAddress(&pX16, g_x16);
    cudaGetSymbolAddress(&pWgu, g_wgu);
    cudaGetSymbolAddress(&pWdn, g_wdn);

    // 1) router
    zero_cnt_kernel<<<1, 32>>>((int*)pCnt);
    router_kernel<<<T_TOKENS / 8, 256>>>(x, gw, (int*)pCnt, (int*)pTok,
                                         (int4*)pTk2, (float2*)pW2);

    // 2) conversions / repacks
    cvt_x_kernel<<<(T_TOKENS * D_DIM) / 1024, 256>>>(x, (fp16*)pX16);
    repack_wgu_kernel<<<dim3(GUP, NSLOT), 256>>>(sgu, egu, (fp16*)pWgu);
    repack_wdn_kernel<<<dim3(D_DIM, NSLOT), 240>>>(sdn, edn, (fp16*)pWdn);

    // 3) GEMM1 + fused swiglu (shared + routed)
    gemm1_kernel<<<dim3(GUP / BN, T_TOKENS / BM, NSLOT), 256, SMEM_DYN>>>();

    // 4) GEMM2: slot 0 writes out, slots 1..8 write ybuf (fp16)
    gemm2_kernel<<<dim3(D_DIM / BN, T_TOKENS / BM, NSLOT), 256, SMEM_DYN>>>(out);

    // 5) combine routed contributions (atomic-free)
    combine_kernel<<<T_TOKENS, 256>>>(out);
}

// round 8
// speedup vs baseline: 2.4619x; 1.0062x over previous
#include <cuda_runtime.h>
#include <cuda_fp16.h>
#include <math.h>
#include <stdint.h>

typedef __half fp16;

#define T_TOKENS 8192
#define D_DIM    1024
#define E_EXP    8
#define I_DIM    938
#define GU_DIM   1876
#define GUP      1920      // 2I padded (15*128)
#define IP       960       // I padded (15*64)
#define NSLOT    9         // slot0 = shared, 1..8 = routed

#define BM 128
#define BN 128
#define BK 64
#define SROW 144                        // 64 fp16 = 128B data + 16B pad
#define OFF_A 0
#define OFF_B (BM*SROW)                 // 18432
#define STAGEB ((BM+BN)*SROW)           // 36864
#define NSTAGE 3
#define SMEM_DYN (1024 + NSTAGE*STAGEB) // 111616

// ---------------- static scratch ----------------
__device__ int    g_cnt[E_EXP];
__device__ int    g_tok[E_EXP * T_TOKENS];
__device__ int4   g_tk2[T_TOKENS];
__device__ float2 g_w2 [T_TOKENS];
__device__ fp16   g_x16[T_TOKENS * D_DIM];
__device__ fp16   g_wgu[NSLOT * GUP * D_DIM];     // interleaved (gate_i, up_i) rows
__device__ fp16   g_wdn[NSLOT * D_DIM * IP];
__device__ fp16   g_act[(size_t)NSLOT * T_TOKENS * IP];
__device__ fp16   g_ybuf[(size_t)E_EXP * T_TOKENS * D_DIM];

// ---------------- helpers ----------------
__device__ __forceinline__ uint32_t smem_u32(const void* p) {
    uint32_t a;
    asm("{ .reg .u64 t; cvta.to.shared.u64 t, %1; cvt.u32.u64 %0, t; }" : "=r"(a) : "l"(p));
    return a;
}
__device__ __forceinline__ void cp16(uint32_t s, const void* g) {
    asm volatile("cp.async.cg.shared.global [%0], [%1], 16;" :: "r"(s), "l"(g));
}
__device__ __forceinline__ void ldsm4(uint32_t* r, uint32_t a) {
    asm volatile("ldmatrix.sync.aligned.m8n8.x4.shared.b16 {%0,%1,%2,%3}, [%4];"
        : "=r"(r[0]), "=r"(r[1]), "=r"(r[2]), "=r"(r[3]) : "r"(a));
}
__device__ __forceinline__ void mma16816(float* d, const uint32_t* a, const uint32_t* b) {
    asm volatile(
        "mma.sync.aligned.m16n8k16.row.col.f32.f16.f16.f32 "
        "{%0,%1,%2,%3}, {%4,%5,%6,%7}, {%8,%9}, {%0,%1,%2,%3};"
        : "+f"(d[0]), "+f"(d[1]), "+f"(d[2]), "+f"(d[3])
        : "r"(a[0]), "r"(a[1]), "r"(a[2]), "r"(a[3]), "r"(b[0]), "r"(b[1]));
}

// ---------- mainloop: 128x128 CTA tile, 64x32 warp tile, 3-stage, 1 sync/chunk --------
__device__ __forceinline__ void gemm_mainloop(
    uint32_t s0,
    const fp16* sa,                       // per-thread A row ptr (row = tid>>1)
    const fp16* sb,                       // per-thread B row ptr (row = tid>>1)
    int NC, int tid, float acc[4][4][4])
{
    const int lane = tid & 31, wid = tid >> 5;
    const uint32_t rowoff = (uint32_t)(tid >> 1) * SROW + (uint32_t)(tid & 1) * 64;
    const int kel = (tid & 1) * 32;

#define LOAD_STAGE(st, c) do {                                              \
        uint32_t base_ = s0 + (st) * STAGEB;                                \
        int k0_ = (c) * BK + kel;                                           \
        _Pragma("unroll")                                                   \
        for (int j = 0; j < 4; j++) {                                       \
            cp16(base_ + OFF_A + rowoff + j*16, sa + k0_ + j*8);            \
            cp16(base_ + OFF_B + rowoff + j*16, sb + k0_ + j*8);            \
        }                                                                   \
        asm volatile("cp.async.commit_group;" ::: "memory");                \
    } while (0)

    LOAD_STAGE(0, 0);
    LOAD_STAGE(1, 1);    // NC >= 2 always here (min NC = 15)

    const int mwb = (wid >> 2) * 64;
    const int nwb = (wid & 3) * 32;
    const int arow   = mwb + (lane & 15);
    const int acolB0 = (lane >> 4) * 16;
    const int bnrow  = nwb + ((lane >> 4) * 8) + (lane & 7);
    const int bkB0   = ((lane >> 3) & 1) * 16;

    int st = 0;
    for (int c = 0; c < NC; c++) {
        if (c + 1 < NC) asm volatile("cp.async.wait_group 1;" ::: "memory");
        else            asm volatile("cp.async.wait_group 0;" ::: "memory");
        __syncthreads();
        if (c + 2 < NC) {
            int ls = st + 2; if (ls >= NSTAGE) ls -= NSTAGE;
            LOAD_STAGE(ls, c + 2);
        }
        const uint32_t tb = s0 + st * STAGEB;
#pragma unroll
        for (int ks = 0; ks < 4; ks++) {
            const uint32_t acolB = ks * 32 + acolB0;
            const uint32_t bcolB = ks * 32 + bkB0;
            uint32_t ah[4][4];
#pragma unroll
            for (int mi = 0; mi < 4; mi++)
                ldsm4(ah[mi], tb + OFF_A + (uint32_t)(arow + mi * 16) * SROW + acolB);
#pragma unroll
            for (int nb = 0; nb < 2; nb++) {
                uint32_t bh[4];
                ldsm4(bh, tb + OFF_B + (uint32_t)(bnrow + nb * 16) * SROW + bcolB);
#pragma unroll
                for (int mi = 0; mi < 4; mi++) {
                    mma16816(acc[mi][nb * 2 + 0], ah[mi], bh + 0);
                    mma16816(acc[mi][nb * 2 + 1], ah[mi], bh + 2);
                }
            }
        }
        st++; if (st == NSTAGE) st = 0;
    }
#undef LOAD_STAGE
}

// ---------------- GEMM1: H = X @ Wgu^T, fused swiglu -> act fp16 ----------------
__global__ void __launch_bounds__(256, 2) gemm1_kernel() {
    extern __shared__ char smem[];
    int* rowids = (int*)smem;
    const uint32_t s0 = smem_u32(smem) + 1024;
    const int tid = threadIdx.x;
    const int s = blockIdx.z, m0 = blockIdx.y * BM, n0 = blockIdx.x * BN;
    const int M = (s == 0) ? T_TOKENS : g_cnt[s - 1];
    if (m0 >= M) return;

    if (tid < BM) {
        int am = m0 + tid;
        int r;
        if (s == 0) r = (am < M ? am : M - 1);
        else        r = g_tok[(s - 1) * T_TOKENS + (am < M ? am : M - 1)];
        rowids[tid] = r;
    }
    __syncthreads();

    const fp16* sa = g_x16 + (long long)rowids[tid >> 1] * D_DIM;
    const fp16* sb = g_wgu + ((long long)s * GUP + n0 + (tid >> 1)) * D_DIM;

    float acc[4][4][4];
#pragma unroll
    for (int i = 0; i < 4; i++)
#pragma unroll
        for (int j = 0; j < 4; j++)
#pragma unroll
            for (int k = 0; k < 4; k++) acc[i][j][k] = 0.f;

    gemm_mainloop(s0, sa, sb, D_DIM / BK, tid, acc);

    const int lane = tid & 31, wid = tid >> 5;
    const int mwb = (wid >> 2) * 64, nwb = (wid & 3) * 32;
    fp16* oa = g_act + (size_t)s * T_TOKENS * IP;
#pragma unroll
    for (int mi = 0; mi < 4; mi++) {
        const int r0 = m0 + mwb + mi * 16 + (lane >> 2);
#pragma unroll
        for (int j = 0; j < 4; j++) {
            const int nbase = n0 + nwb + j * 8 + (lane & 3) * 2;
            const int acol = nbase >> 1;
            const float* a = acc[mi][j];
            if (r0 < M) {
                float g = a[0], u = a[1];
                float v = (g / (1.f + __expf(-g))) * u;
                oa[(size_t)r0 * IP + acol] = __float2half(v);
            }
            if (r0 + 8 < M) {
                float g = a[2], u = a[3];
                float v = (g / (1.f + __expf(-g))) * u;
                oa[(size_t)(r0 + 8) * IP + acol] = __float2half(v);
            }
        }
    }
}

// ---------------- GEMM2: C = act @ down^T (slot0 -> out fp32, 1..8 -> ybuf fp16) ------
__global__ void __launch_bounds__(256, 2) gemm2_kernel(float* __restrict__ out) {
    extern __shared__ char smem[];
    const uint32_t s0 = smem_u32(smem) + 1024;
    const int tid = threadIdx.x;
    const int s = blockIdx.z, m0 = blockIdx.y * BM, n0 = blockIdx.x * BN;
    const int M = (s == 0) ? T_TOKENS : g_cnt[s - 1];
    if (m0 >= M) return;

    const int amr = m0 + (tid >> 1) < T_TOKENS ? m0 + (tid >> 1) : T_TOKENS - 1;
    const fp16* sa = g_act + (size_t)s * T_TOKENS * IP + (size_t)amr * IP;
    const fp16* sb = g_wdn + ((long long)s * D_DIM + n0 + (tid >> 1)) * IP;

    float acc[4][4][4];
#pragma unroll
    for (int i = 0; i < 4; i++)
#pragma unroll
        for (int j = 0; j < 4; j++)
#pragma unroll
            for (int k = 0; k < 4; k++) acc[i][j][k] = 0.f;

    gemm_mainloop(s0, sa, sb, IP / BK, tid, acc);

    const int lane = tid & 31, wid = tid >> 5;
    const int mwb = (wid >> 2) * 64, nwb = (wid & 3) * 32;
    if (s == 0) {
#pragma unroll
        for (int mi = 0; mi < 4; mi++) {
            const int r0 = m0 + mwb + mi * 16 + (lane >> 2);
#pragma unroll
            for (int j = 0; j < 4; j++) {
                const int n = n0 + nwb + j * 8 + (lane & 3) * 2;
                const float* a = acc[mi][j];
                if (r0 < M)     *(float2*)(out + (size_t)r0 * D_DIM + n)       = make_float2(a[0], a[1]);
                if (r0 + 8 < M) *(float2*)(out + (size_t)(r0 + 8) * D_DIM + n) = make_float2(a[2], a[3]);
            }
        }
    } else {
        fp16* C = g_ybuf + (size_t)(s - 1) * T_TOKENS * D_DIM;
#pragma unroll
        for (int mi = 0; mi < 4; mi++) {
            const int r0 = m0 + mwb + mi * 16 + (lane >> 2);
#pragma unroll
            for (int j = 0; j < 4; j++) {
                const int n = n0 + nwb + j * 8 + (lane & 3) * 2;
                const float* a = acc[mi][j];
                if (r0 < M) {
                    __align__(4) fp16 h[2] = {__float2half(a[0]), __float2half(a[1])};
                    *(uint32_t*)(C + (size_t)r0 * D_DIM + n) = *(const uint32_t*)h;
                }
                if (r0 + 8 < M) {
                    __align__(4) fp16 h[2] = {__float2half(a[2]), __float2half(a[3])};
                    *(uint32_t*)(C + (size_t)(r0 + 8) * D_DIM + n) = *(const uint32_t*)h;
                }
            }
        }
    }
}

// ---------------- combine: out[t] += w1*y[e1][p1] + w2*y[e2][p2] (fp16 ybuf) ----------
__global__ void combine_kernel(float* __restrict__ out) {
    const int t = blockIdx.x;
    const int c = threadIdx.x;                // 256 threads x 4 floats = 1024
    const int4 e = g_tk2[t];
    const float2 w = g_w2[t];
    const uint2* y1 = (const uint2*)(g_ybuf + ((size_t)e.x * T_TOKENS + e.y) * D_DIM);
    const uint2* y2 = (const uint2*)(g_ybuf + ((size_t)e.z * T_TOKENS + e.w) * D_DIM);
    float4* o = (float4*)(out + (size_t)t * D_DIM);
    uint2 p1 = y1[c], p2 = y2[c];
    float2 a1 = __half22float2(*(const __half2*)&p1.x);
    float2 b1 = __half22float2(*(const __half2*)&p1.y);
    float2 a2 = __half22float2(*(const __half2*)&p2.x);
    float2 b2 = __half22float2(*(const __half2*)&p2.y);
    float4 a = o[c];
    a.x += w.x * a1.x + w.y * a2.x;
    a.y += w.x * a1.y + w.y * a2.y;
    a.z += w.x * b1.x + w.y * b2.x;
    a.w += w.x * b1.y + w.y * b2.y;
    o[c] = a;
}

// ---------------- prep kernels ----------------
__global__ void zero_cnt_kernel(int* cnt) {
    if (threadIdx.x < E_EXP) cnt[threadIdx.x] = 0;
}

__global__ void cvt_x_kernel(const float* __restrict__ x, fp16* __restrict__ xo) {
    const int i4 = (blockIdx.x * 256 + threadIdx.x) * 4;
    float4 v = *(const float4*)(x + i4);
    __align__(8) fp16 h[4];
    h[0] = __float2half(v.x); h[1] = __float2half(v.y);
    h[2] = __float2half(v.z); h[3] = __float2half(v.w);
    *(uint2*)(xo + i4) = *(const uint2*)h;
}

// grid (GUP, NSLOT), block 256
__global__ void repack_wgu_kernel(const float* __restrict__ sgu, const float* __restrict__ egu,
                                  fp16* __restrict__ w) {
    const int r = blockIdx.x, s = blockIdx.y;
    const int k4 = threadIdx.x * 4;
    const size_t dst = ((size_t)s * GUP + r) * D_DIM + k4;
    float4 v = make_float4(0.f, 0.f, 0.f, 0.f);
    if (r < GU_DIM) {
        const int sr = (r & 1) ? (r >> 1) + I_DIM : (r >> 1);
        const float* src = (s == 0) ? (sgu + (size_t)sr * D_DIM)
                                    : (egu + ((size_t)(s - 1) * GU_DIM + sr) * D_DIM);
        v = *(const float4*)(src + k4);
    }
    __align__(8) fp16 h[4];
    h[0] = __float2half(v.x); h[1] = __float2half(v.y);
    h[2] = __float2half(v.z); h[3] = __float2half(v.w);
    *(uint2*)(w + dst) = *(const uint2*)h;
}

// grid (D_DIM, NSLOT), block 240
__global__ void repack_wdn_kernel(const float* __restrict__ sdn, const float* __restrict__ edn,
                                  fp16* __restrict__ w) {
    const int n = blockIdx.x, s = blockIdx.y;
    const int k4 = threadIdx.x * 4;
    const size_t dst = ((size_t)s * D_DIM + n) * IP + k4;
    const float* src = (s == 0) ? (sdn + (size_t)n * I_DIM)
                                : (edn + ((size_t)(s - 1) * D_DIM + n) * I_DIM);
    __align__(8) fp16 h[4];
#pragma unroll
    for (int q = 0; q < 4; q++) {
        const int i = k4 + q;
        float v = (i < I_DIM) ? __ldg(src + i) : 0.f;
        h[q] = __float2half(v);
    }
    *(uint2*)(w + dst) = *(const uint2*)h;
}

// ---------------- router (fp32, bit-identical routing) ----------------
__global__ void router_kernel(const float* __restrict__ x, const float* __restrict__ gw,
                              int* __restrict__ cnt, int* __restrict__ tok,
                              int4* __restrict__ tk2, float2* __restrict__ w2) {
    __shared__ float sgw[E_EXP * D_DIM];
    const int tid = threadIdx.x;
    for (int i = tid; i < E_EXP * D_DIM; i += blockDim.x) sgw[i] = gw[i];
    __syncthreads();
    const int warp = tid >> 5, lane = tid & 31;
    const int t = blockIdx.x * 8 + warp;
    const float* xt = x + (long long)t * D_DIM;
    float acc[E_EXP];
#pragma unroll
    for (int e = 0; e < E_EXP; e++) acc[e] = 0.f;
    for (int k = lane; k < D_DIM; k += 32) {
        float xv = xt[k];
#pragma unroll
        for (int e = 0; e < E_EXP; e++) acc[e] += xv * sgw[e * D_DIM + k];
    }
#pragma unroll
    for (int e = 0; e < E_EXP; e++)
#pragma unroll
        for (int off = 16; off; off >>= 1)
            acc[e] += __shfl_xor_sync(0xffffffffu, acc[e], off);
    if (lane == 0) {
        float mx = acc[0];
#pragma unroll
        for (int e = 1; e < E_EXP; e++) mx = fmaxf(mx, acc[e]);
        float p[E_EXP], Z = 0.f;
#pragma unroll
        for (int e = 0; e < E_EXP; e++) { p[e] = expf(acc[e] - mx); Z += p[e]; }
#pragma unroll
        for (int e = 0; e < E_EXP; e++) p[e] /= Z;
        int i1 = 0;
#pragma unroll
        for (int e = 1; e < E_EXP; e++) if (p[e] > p[i1]) i1 = e;
        int i2 = (i1 == 0) ? 1 : 0;
#pragma unroll
        for (int e = 0; e < E_EXP; e++) if (e != i1 && e != i2 && p[e] > p[i2]) i2 = e;
        float denom = p[i1] + p[i2] + 1e-8f;
        int pos1 = atomicAdd(&cnt[i1], 1);
        tok[i1 * T_TOKENS + pos1] = t;
        int pos2 = atomicAdd(&cnt[i2], 1);
        tok[i2 * T_TOKENS + pos2] = t;
        tk2[t] = make_int4(i1, pos1, i2, pos2);
        w2[t]  = make_float2(p[i1] / denom, p[i2] / denom);
    }
}

// ---------------- host launch ----------------
extern "C" void kernel_launch(void* const* d_in, const int* in_sizes, int n_in,
                              void* d_out, int out_size) {
    const float* x   = (const float*)d_in[0];
    const float* gw  = (const float*)d_in[1];
    const float* sgu = (const float*)d_in[2];
    const float* sdn = (const float*)d_in[3];
    const float* egu = (const float*)d_in[4];
    const float* edn = (const float*)d_in[5];
    float* out = (float*)d_out;

    cudaFuncSetAttribute(gemm1_kernel, cudaFuncAttributeMaxDynamicSharedMemorySize, SMEM_DYN);
    cudaFuncSetAttribute(gemm2_kernel, cudaFuncAttributeMaxDynamicSharedMemorySize, SMEM_DYN);

    void *pCnt, *pTok, *pTk2, *pW2, *pX16, *pWgu, *pWdn;
    cudaGetSymbolAddress(&pCnt, g_cnt);
    cudaGetSymbolAddress(&pTok, g_tok);
    cudaGetSymbolAddress(&pTk2, g_tk2);
    cudaGetSymbolAddress(&pW2,  g_w2);
    cudaGetSymbolAddress(&pX16, g_x16);
    cudaGetSymbolAddress(&pWgu, g_wgu);
    cudaGetSymbolAddress(&pWdn, g_wdn);

    // 1-3) conversions / repacks first (launch order also places gemm1 at
    //      ncu's profile slot: skip 5 -> captures launch #6 = gemm1)
    cvt_x_kernel<<<(T_TOKENS * D_DIM) / 1024, 256>>>(x, (fp16*)pX16);
    repack_wgu_kernel<<<dim3(GUP, NSLOT), 256>>>(sgu, egu, (fp16*)pWgu);
    repack_wdn_kernel<<<dim3(D_DIM, NSLOT), 240>>>(sdn, edn, (fp16*)pWdn);

    // 4-5) router
    zero_cnt_kernel<<<1, 32>>>((int*)pCnt);
    router_kernel<<<T_TOKENS / 8, 256>>>(x, gw, (int*)pCnt, (int*)pTok,
                                         (int4*)pTk2, (float2*)pW2);

    // 6) GEMM1 + fused swiglu (shared + routed)
    gemm1_kernel<<<dim3(GUP / BN, T_TOKENS / BM, NSLOT), 256, SMEM_DYN>>>();

    // 7) GEMM2: slot 0 writes out, slots 1..8 write ybuf (fp16)
    gemm2_kernel<<<dim3(D_DIM / BN, T_TOKENS / BM, NSLOT), 256, SMEM_DYN>>>(out);

    // 8) combine routed contributions (atomic-free)
    combine_kernel<<<T_TOKENS, 256>>>(out);
}

// round 9
// speedup vs baseline: 2.4688x; 1.0028x over previous
#include <cuda_runtime.h>
#include <cuda_fp16.h>
#include <math.h>
#include <stdint.h>

typedef __half fp16;

#define T_TOKENS 8192
#define D_DIM    1024
#define E_EXP    8
#define I_DIM    938
#define GU_DIM   1876
#define GUP      1920      // 2I padded (15*128)
#define IP       960       // I padded (15*64)
#define NSLOT    9         // slot0 = shared, 1..8 = routed

#define BM 128
#define BN 128
#define BK 64
#define SROW 144                        // 64 fp16 = 128B data + 16B pad
#define OFF_A 0
#define OFF_B (BM*SROW)                 // 18432
#define STAGEB ((BM+BN)*SROW)           // 36864
#define NSTAGE 3
#define SMEM_DYN (1024 + NSTAGE*STAGEB) // 111616

// ---------------- static scratch ----------------
__device__ int    g_cnt[E_EXP];
__device__ int    g_tok[E_EXP * T_TOKENS];
__device__ int4   g_tk2[T_TOKENS];
__device__ float2 g_w2 [T_TOKENS];
__device__ fp16   g_x16[T_TOKENS * D_DIM];
__device__ fp16   g_wgu[NSLOT * GUP * D_DIM];     // interleaved (gate_i, up_i) rows
__device__ fp16   g_wdn[NSLOT * D_DIM * IP];
__device__ fp16   g_act[(size_t)NSLOT * T_TOKENS * IP];
__device__ fp16   g_ybuf[(size_t)E_EXP * T_TOKENS * D_DIM];

// ---------------- helpers ----------------
__device__ __forceinline__ uint32_t smem_u32(const void* p) {
    uint32_t a;
    asm("{ .reg .u64 t; cvta.to.shared.u64 t, %1; cvt.u32.u64 %0, t; }" : "=r"(a) : "l"(p));
    return a;
}
__device__ __forceinline__ void cp16(uint32_t s, const void* g) {
    asm volatile("cp.async.cg.shared.global [%0], [%1], 16;" :: "r"(s), "l"(g));
}
__device__ __forceinline__ void ldsm4(uint32_t* r, uint32_t a) {
    asm volatile("ldmatrix.sync.aligned.m8n8.x4.shared.b16 {%0,%1,%2,%3}, [%4];"
        : "=r"(r[0]), "=r"(r[1]), "=r"(r[2]), "=r"(r[3]) : "r"(a));
}
__device__ __forceinline__ void mma16816(float* d, const uint32_t* a, const uint32_t* b) {
    asm volatile(
        "mma.sync.aligned.m16n8k16.row.col.f32.f16.f16.f32 "
        "{%0,%1,%2,%3}, {%4,%5,%6,%7}, {%8,%9}, {%0,%1,%2,%3};"
        : "+f"(d[0]), "+f"(d[1]), "+f"(d[2]), "+f"(d[3])
        : "r"(a[0]), "r"(a[1]), "r"(a[2]), "r"(a[3]), "r"(b[0]), "r"(b[1]));
}

// ---------- mainloop: 128x128 CTA tile, 64x32 warp tile, 3-stage, 1 sync/chunk --------
__device__ __forceinline__ void gemm_mainloop(
    uint32_t s0,
    const fp16* sa,                       // per-thread A row ptr (row = tid>>1)
    const fp16* sb,                       // per-thread B row ptr (row = tid>>1)
    int NC, int tid, float acc[4][4][4])
{
    const int lane = tid & 31, wid = tid >> 5;
    const uint32_t rowoff = (uint32_t)(tid >> 1) * SROW + (uint32_t)(tid & 1) * 64;
    const int kel = (tid & 1) * 32;

#define LOAD_STAGE(st, c) do {                                              \
        uint32_t base_ = s0 + (st) * STAGEB;                                \
        int k0_ = (c) * BK + kel;                                           \
        _Pragma("unroll")                                                   \
        for (int j = 0; j < 4; j++) {                                       \
            cp16(base_ + OFF_A + rowoff + j*16, sa + k0_ + j*8);            \
            cp16(base_ + OFF_B + rowoff + j*16, sb + k0_ + j*8);            \
        }                                                                   \
        asm volatile("cp.async.commit_group;" ::: "memory");                \
    } while (0)

    LOAD_STAGE(0, 0);
    LOAD_STAGE(1, 1);    // NC >= 2 always (min NC = 15)

    const int mwb = (wid >> 2) * 64;
    const int nwb = (wid & 3) * 32;
    const int arow   = mwb + (lane & 15);
    const int acolB0 = (lane >> 4) * 16;
    const int bnrow  = nwb + ((lane >> 4) * 8) + (lane & 7);
    const int bkB0   = ((lane >> 3) & 1) * 16;

    int st = 0;
    for (int c = 0; c < NC; c++) {
        if (c + 1 < NC) asm volatile("cp.async.wait_group 1;" ::: "memory");
        else            asm volatile("cp.async.wait_group 0;" ::: "memory");
        __syncthreads();
        if (c + 2 < NC) {
            int ls = st + 2; if (ls >= NSTAGE) ls -= NSTAGE;
            LOAD_STAGE(ls, c + 2);
        }
        const uint32_t tb = s0 + st * STAGEB;
#pragma unroll
        for (int ks = 0; ks < 4; ks++) {
            const uint32_t acolB = ks * 32 + acolB0;
            const uint32_t bcolB = ks * 32 + bkB0;
            uint32_t ah[4][4];
#pragma unroll
            for (int mi = 0; mi < 4; mi++)
                ldsm4(ah[mi], tb + OFF_A + (uint32_t)(arow + mi * 16) * SROW + acolB);
#pragma unroll
            for (int nb = 0; nb < 2; nb++) {
                uint32_t bh[4];
                ldsm4(bh, tb + OFF_B + (uint32_t)(bnrow + nb * 16) * SROW + bcolB);
#pragma unroll
                for (int mi = 0; mi < 4; mi++) {
                    mma16816(acc[mi][nb * 2 + 0], ah[mi], bh + 0);
                    mma16816(acc[mi][nb * 2 + 1], ah[mi], bh + 2);
                }
            }
        }
        st++; if (st == NSTAGE) st = 0;
    }
#undef LOAD_STAGE
}

// ---------------- GEMM1: H = X @ Wgu^T, fused swiglu -> act fp16 ----------------
__global__ void __launch_bounds__(256, 2) gemm1_kernel() {
    extern __shared__ char smem[];
    int* rowids = (int*)smem;
    const uint32_t s0 = smem_u32(smem) + 1024;
    const int tid = threadIdx.x;
    const int s = blockIdx.z, m0 = blockIdx.y * BM, n0 = blockIdx.x * BN;
    const int M = (s == 0) ? T_TOKENS : g_cnt[s - 1];
    if (m0 >= M) return;

    if (tid < BM) {
        int am = m0 + tid;
        int r;
        if (s == 0) r = (am < M ? am : M - 1);
        else        r = g_tok[(s - 1) * T_TOKENS + (am < M ? am : M - 1)];
        rowids[tid] = r;
    }
    __syncthreads();

    const fp16* sa = g_x16 + (long long)rowids[tid >> 1] * D_DIM;
    const fp16* sb = g_wgu + ((long long)s * GUP + n0 + (tid >> 1)) * D_DIM;

    float acc[4][4][4];
#pragma unroll
    for (int i = 0; i < 4; i++)
#pragma unroll
        for (int j = 0; j < 4; j++)
#pragma unroll
            for (int k = 0; k < 4; k++) acc[i][j][k] = 0.f;

    gemm_mainloop(s0, sa, sb, D_DIM / BK, tid, acc);

    const int lane = tid & 31, wid = tid >> 5;
    const int mwb = (wid >> 2) * 64, nwb = (wid & 3) * 32;
    fp16* oa = g_act + (size_t)s * T_TOKENS * IP;
#pragma unroll
    for (int mi = 0; mi < 4; mi++) {
        const int r0 = m0 + mwb + mi * 16 + (lane >> 2);
#pragma unroll
        for (int j = 0; j < 4; j++) {
            const int nbase = n0 + nwb + j * 8 + (lane & 3) * 2;
            const int acol = nbase >> 1;
            const float* a = acc[mi][j];
            if (r0 < M) {
                float g = a[0], u = a[1];
                float v = (g / (1.f + __expf(-g))) * u;
                oa[(size_t)r0 * IP + acol] = __float2half(v);
            }
            if (r0 + 8 < M) {
                float g = a[2], u = a[3];
                float v = (g / (1.f + __expf(-g))) * u;
                oa[(size_t)(r0 + 8) * IP + acol] = __float2half(v);
            }
        }
    }
}

// ---------------- GEMM2: C = act @ down^T (slot0 -> out fp32, 1..8 -> ybuf fp16) ------
__global__ void __launch_bounds__(256, 2) gemm2_kernel(float* __restrict__ out) {
    extern __shared__ char smem[];
    const uint32_t s0 = smem_u32(smem) + 1024;
    const int tid = threadIdx.x;
    const int s = blockIdx.z, m0 = blockIdx.y * BM, n0 = blockIdx.x * BN;
    const int M = (s == 0) ? T_TOKENS : g_cnt[s - 1];
    if (m0 >= M) return;

    const int amr = m0 + (tid >> 1) < T_TOKENS ? m0 + (tid >> 1) : T_TOKENS - 1;
    const fp16* sa = g_act + (size_t)s * T_TOKENS * IP + (size_t)amr * IP;
    const fp16* sb = g_wdn + ((long long)s * D_DIM + n0 + (tid >> 1)) * IP;

    float acc[4][4][4];
#pragma unroll
    for (int i = 0; i < 4; i++)
#pragma unroll
        for (int j = 0; j < 4; j++)
#pragma unroll
            for (int k = 0; k < 4; k++) acc[i][j][k] = 0.f;

    gemm_mainloop(s0, sa, sb, IP / BK, tid, acc);

    const int lane = tid & 31, wid = tid >> 5;
    const int mwb = (wid >> 2) * 64, nwb = (wid & 3) * 32;
    if (s == 0) {
#pragma unroll
        for (int mi = 0; mi < 4; mi++) {
            const int r0 = m0 + mwb + mi * 16 + (lane >> 2);
#pragma unroll
            for (int j = 0; j < 4; j++) {
                const int n = n0 + nwb + j * 8 + (lane & 3) * 2;
                const float* a = acc[mi][j];
                if (r0 < M)     *(float2*)(out + (size_t)r0 * D_DIM + n)       = make_float2(a[0], a[1]);
                if (r0 + 8 < M) *(float2*)(out + (size_t)(r0 + 8) * D_DIM + n) = make_float2(a[2], a[3]);
            }
        }
    } else {
        fp16* C = g_ybuf + (size_t)(s - 1) * T_TOKENS * D_DIM;
#pragma unroll
        for (int mi = 0; mi < 4; mi++) {
            const int r0 = m0 + mwb + mi * 16 + (lane >> 2);
#pragma unroll
            for (int j = 0; j < 4; j++) {
                const int n = n0 + nwb + j * 8 + (lane & 3) * 2;
                const float* a = acc[mi][j];
                if (r0 < M) {
                    __align__(4) fp16 h[2] = {__float2half(a[0]), __float2half(a[1])};
                    *(uint32_t*)(C + (size_t)r0 * D_DIM + n) = *(const uint32_t*)h;
                }
                if (r0 + 8 < M) {
                    __align__(4) fp16 h[2] = {__float2half(a[2]), __float2half(a[3])};
                    *(uint32_t*)(C + (size_t)(r0 + 8) * D_DIM + n) = *(const uint32_t*)h;
                }
            }
        }
    }
}

// ---------------- combine: out[t] += w1*y[e1][p1] + w2*y[e2][p2] (fp16 ybuf) ----------
__global__ void combine_kernel(float* __restrict__ out) {
    const int t = blockIdx.x;
    const int c = threadIdx.x;                // 256 threads x 4 floats = 1024
    const int4 e = g_tk2[t];
    const float2 w = g_w2[t];
    const uint2* y1 = (const uint2*)(g_ybuf + ((size_t)e.x * T_TOKENS + e.y) * D_DIM);
    const uint2* y2 = (const uint2*)(g_ybuf + ((size_t)e.z * T_TOKENS + e.w) * D_DIM);
    float4* o = (float4*)(out + (size_t)t * D_DIM);
    uint2 p1 = y1[c], p2 = y2[c];
    float2 a1 = __half22float2(*(const __half2*)&p1.x);
    float2 b1 = __half22float2(*(const __half2*)&p1.y);
    float2 a2 = __half22float2(*(const __half2*)&p2.x);
    float2 b2 = __half22float2(*(const __half2*)&p2.y);
    float4 a = o[c];
    a.x += w.x * a1.x + w.y * a2.x;
    a.y += w.x * a1.y + w.y * a2.y;
    a.z += w.x * b1.x + w.y * b2.x;
    a.w += w.x * b1.y + w.y * b2.y;
    o[c] = a;
}

// ---------------- fused prep A: cvt_x + zero counters ----------------
__global__ void prepA_kernel(const float* __restrict__ x, fp16* __restrict__ xo,
                             int* __restrict__ cnt) {
    if (blockIdx.x == 0 && threadIdx.x < E_EXP) cnt[threadIdx.x] = 0;
    const int i4 = (blockIdx.x * 256 + threadIdx.x) * 4;
    float4 v = *(const float4*)(x + i4);
    __align__(8) fp16 h[4];
    h[0] = __float2half(v.x); h[1] = __float2half(v.y);
    h[2] = __float2half(v.z); h[3] = __float2half(v.w);
    *(uint2*)(xo + i4) = *(const uint2*)h;
}

// ---------------- fused prep B: repack wgu + wdn ----------------
// grid ((GUP + D_DIM), NSLOT), block 256
__global__ void prepB_kernel(const float* __restrict__ sgu, const float* __restrict__ egu,
                             const float* __restrict__ sdn, const float* __restrict__ edn,
                             fp16* __restrict__ wgu, fp16* __restrict__ wdn) {
    const int s = blockIdx.y;
    if (blockIdx.x < GUP) {
        const int r = blockIdx.x;
        const int k4 = threadIdx.x * 4;
        const size_t dst = ((size_t)s * GUP + r) * D_DIM + k4;
        float4 v = make_float4(0.f, 0.f, 0.f, 0.f);
        if (r < GU_DIM) {
            const int sr = (r & 1) ? (r >> 1) + I_DIM : (r >> 1);
            const float* src = (s == 0) ? (sgu + (size_t)sr * D_DIM)
                                        : (egu + ((size_t)(s - 1) * GU_DIM + sr) * D_DIM);
            v = *(const float4*)(src + k4);
        }
        __align__(8) fp16 h[4];
        h[0] = __float2half(v.x); h[1] = __float2half(v.y);
        h[2] = __float2half(v.z); h[3] = __float2half(v.w);
        *(uint2*)(wgu + dst) = *(const uint2*)h;
    } else {
        if (threadIdx.x >= 240) return;
        const int n = blockIdx.x - GUP;
        const int k4 = threadIdx.x * 4;
        const size_t dst = ((size_t)s * D_DIM + n) * IP + k4;
        const float* src = (s == 0) ? (sdn + (size_t)n * I_DIM)
                                    : (edn + ((size_t)(s - 1) * D_DIM + n) * I_DIM);
        __align__(8) fp16 h[4];
#pragma unroll
        for (int q = 0; q < 4; q++) {
            const int i = k4 + q;
            float v = (i < I_DIM) ? __ldg(src + i) : 0.f;
            h[q] = __float2half(v);
        }
        *(uint2*)(wdn + dst) = *(const uint2*)h;
    }
}

// ---------------- router (fp32, bit-identical routing) ----------------
__global__ void router_kernel(const float* __restrict__ x, const float* __restrict__ gw,
                              int* __restrict__ cnt, int* __restrict__ tok,
                              int4* __restrict__ tk2, float2* __restrict__ w2) {
    __shared__ float sgw[E_EXP * D_DIM];
    const int tid = threadIdx.x;
    for (int i = tid; i < E_EXP * D_DIM; i += blockDim.x) sgw[i] = gw[i];
    __syncthreads();
    const int warp = tid >> 5, lane = tid & 31;
    const int t = blockIdx.x * 8 + warp;
    const float* xt = x + (long long)t * D_DIM;
    float acc[E_EXP];
#pragma unroll
    for (int e = 0; e < E_EXP; e++) acc[e] = 0.f;
    for (int k = lane; k < D_DIM; k += 32) {
        float xv = xt[k];
#pragma unroll
        for (int e = 0; e < E_EXP; e++) acc[e] += xv * sgw[e * D_DIM + k];
    }
#pragma unroll
    for (int e = 0; e < E_EXP; e++)
#pragma unroll
        for (int off = 16; off; off >>= 1)
            acc[e] += __shfl_xor_sync(0xffffffffu, acc[e], off);
    if (lane == 0) {
        float mx = acc[0];
#pragma unroll
        for (int e = 1; e < E_EXP; e++) mx = fmaxf(mx, acc[e]);
        float p[E_EXP], Z = 0.f;
#pragma unroll
        for (int e = 0; e < E_EXP; e++) { p[e] = expf(acc[e] - mx); Z += p[e]; }
#pragma unroll
        for (int e = 0; e < E_EXP; e++) p[e] /= Z;
        int i1 = 0;
#pragma unroll
        for (int e = 1; e < E_EXP; e++) if (p[e] > p[i1]) i1 = e;
        int i2 = (i1 == 0) ? 1 : 0;
#pragma unroll
        for (int e = 0; e < E_EXP; e++) if (e != i1 && e != i2 && p[e] > p[i2]) i2 = e;
        float denom = p[i1] + p[i2] + 1e-8f;
        int pos1 = atomicAdd(&cnt[i1], 1);
        tok[i1 * T_TOKENS + pos1] = t;
        int pos2 = atomicAdd(&cnt[i2], 1);
        tok[i2 * T_TOKENS + pos2] = t;
        tk2[t] = make_int4(i1, pos1, i2, pos2);
        w2[t]  = make_float2(p[i1] / denom, p[i2] / denom);
    }
}

// ---------------- host launch ----------------
extern "C" void kernel_launch(void* const* d_in, const int* in_sizes, int n_in,
                              void* d_out, int out_size) {
    const float* x   = (const float*)d_in[0];
    const float* gw  = (const float*)d_in[1];
    const float* sgu = (const float*)d_in[2];
    const float* sdn = (const float*)d_in[3];
    const float* egu = (const float*)d_in[4];
    const float* edn = (const float*)d_in[5];
    float* out = (float*)d_out;

    cudaFuncSetAttribute(gemm1_kernel, cudaFuncAttributeMaxDynamicSharedMemorySize, SMEM_DYN);
    cudaFuncSetAttribute(gemm2_kernel, cudaFuncAttributeMaxDynamicSharedMemorySize, SMEM_DYN);

    void *pCnt, *pTok, *pTk2, *pW2, *pX16, *pWgu, *pWdn;
    cudaGetSymbolAddress(&pCnt, g_cnt);
    cudaGetSymbolAddress(&pTok, g_tok);
    cudaGetSymbolAddress(&pTk2, g_tk2);
    cudaGetSymbolAddress(&pW2,  g_w2);
    cudaGetSymbolAddress(&pX16, g_x16);
    cudaGetSymbolAddress(&pWgu, g_wgu);
    cudaGetSymbolAddress(&pWdn, g_wdn);

    // #1: x -> fp16 + zero counters
    prepA_kernel<<<(T_TOKENS * D_DIM) / 1024, 256>>>(x, (fp16*)pX16, (int*)pCnt);

    // #2: repack both weight sets
    prepB_kernel<<<dim3(GUP + D_DIM, NSLOT), 256>>>(sgu, egu, sdn, edn,
                                                    (fp16*)pWgu, (fp16*)pWdn);

    // #3: router
    router_kernel<<<T_TOKENS / 8, 256>>>(x, gw, (int*)pCnt, (int*)pTok,
                                         (int4*)pTk2, (float2*)pW2);

    // #4: GEMM1 + fused swiglu  (lands on the ncu profile slot)
    gemm1_kernel<<<dim3(GUP / BN, T_TOKENS / BM, NSLOT), 256, SMEM_DYN>>>();

    // #5: GEMM2: slot 0 writes out, slots 1..8 write ybuf (fp16)
    gemm2_kernel<<<dim3(D_DIM / BN, T_TOKENS / BM, NSLOT), 256, SMEM_DYN>>>(out);

    // #6: combine routed contributions (atomic-free)
    combine_kernel<<<T_TOKENS, 256>>>(out);
}